// round 1
// baseline (speedup 1.0000x reference)
#include <cuda_runtime.h>
#include <cuda_bf16.h>
#include <math.h>

// Problem constants
#define B_     16
#define IC_    512
#define OC_    512
#define HW_    32
#define KK_    3
#define STYLE_ 512

#define AFF_SCALE 0.04419417382415922f   // 1/sqrt(512)
#define W_SCALE   0.014731391274719739f  // 1/sqrt(512*9)

// Scratch (device globals; no allocations allowed)
__device__ float g_s  [B_ * IC_];   // s' = (style@affW^T*aff_scale + bias + 1) * w_scale
__device__ float g_s2 [B_ * IC_];   // s'^2
__device__ float g_cw2t[IC_ * OC_]; // transposed: [i][o] = sum_k cw[o,i,k]^2
__device__ float g_d  [B_ * OC_];   // demod factors

// ---------------------------------------------------------------------------
// Kernel 1: style affine  s'[b,i]
// ---------------------------------------------------------------------------
__global__ void affine_kernel(const float* __restrict__ style,
                              const float* __restrict__ aff_w,
                              const float* __restrict__ aff_b) {
    int b = blockIdx.x;
    int i = threadIdx.x;             // 512 threads
    __shared__ float st[STYLE_];
    st[i] = style[b * STYLE_ + i];
    __syncthreads();

    const float* wrow = aff_w + (size_t)i * STYLE_;
    float acc = 0.f;
    #pragma unroll 8
    for (int j = 0; j < STYLE_; j++) acc = fmaf(wrow[j], st[j], acc);

    float s  = acc * AFF_SCALE + aff_b[i] + 1.0f;
    float sp = s * W_SCALE;
    g_s [b * IC_ + i] = sp;
    g_s2[b * IC_ + i] = sp * sp;
}

// ---------------------------------------------------------------------------
// Kernel 2: per-(o,i) weight square sums, stored transposed [i][o]
// ---------------------------------------------------------------------------
__global__ void wsq_kernel(const float* __restrict__ cw) {
    int idx = blockIdx.x * blockDim.x + threadIdx.x;   // o-major for coalesced reads
    if (idx >= OC_ * IC_) return;
    int o = idx / IC_;
    int i = idx - o * IC_;
    const float* p = cw + (size_t)idx * 9;
    float a = 0.f;
    #pragma unroll
    for (int k = 0; k < 9; k++) a = fmaf(p[k], p[k], a);
    g_cw2t[i * OC_ + o] = a;
}

// ---------------------------------------------------------------------------
// Kernel 3: demodulation d[b,o]
// ---------------------------------------------------------------------------
__global__ void demod_kernel() {
    int b = blockIdx.x;
    int o = threadIdx.x;             // 512 threads
    __shared__ float s2[IC_];
    s2[o] = g_s2[b * IC_ + o];
    __syncthreads();

    float a = 0.f;
    #pragma unroll 8
    for (int i = 0; i < IC_; i++) a = fmaf(s2[i], g_cw2t[i * OC_ + o], a);
    g_d[b * OC_ + o] = rsqrtf(a + 1e-8f);
}

// ---------------------------------------------------------------------------
// Kernel 4: conv.  Block = (1 batch, 16 oc, 32x32 spatial). 256 threads.
// Each thread: 4 pixels (rows th0+8p, col tw) x 16 oc accumulators.
// Stages 4 input channels at a time: x halo tile 34x34 (scaled by s'),
// weights 16oc x 4ic x 9 in smem.
// ---------------------------------------------------------------------------
#define OC_TILE 16
#define IC_STEP 4
#define TILE_E  (34 * 34)

__global__ __launch_bounds__(256, 2)
void conv_kernel(const float* __restrict__ x,
                 const float* __restrict__ cw,
                 float* __restrict__ out) {
    const int b      = blockIdx.y;
    const int ocbase = blockIdx.x * OC_TILE;
    const int tid    = threadIdx.x;
    const int tw     = tid & 31;     // output col 0..31
    const int th0    = tid >> 5;     // output row base 0..7 (rows th0 + 8p)

    __shared__ float sx[IC_STEP][TILE_E];
    __shared__ float sw[IC_STEP][OC_TILE][9];

    float acc[4][OC_TILE];
    #pragma unroll
    for (int p = 0; p < 4; p++)
        #pragma unroll
        for (int oc = 0; oc < OC_TILE; oc++) acc[p][oc] = 0.f;

    const float* sb = g_s + b * IC_;

    for (int ic0 = 0; ic0 < IC_; ic0 += IC_STEP) {
        __syncthreads();   // previous iteration's reads done

        // stage x (with per-channel style scale folded in)
        for (int t = tid; t < IC_STEP * TILE_E; t += 256) {
            int icl = t / TILE_E;
            int rc  = t - icl * TILE_E;
            int r   = rc / 34;
            int c   = rc - r * 34;
            int gh  = r - 1, gw = c - 1;
            int ic  = ic0 + icl;
            float v = 0.f;
            if ((unsigned)gh < 32u && (unsigned)gw < 32u)
                v = x[(((size_t)b * IC_ + ic) * HW_ + gh) * HW_ + gw] * sb[ic];
            sx[icl][rc] = v;
        }
        // stage weights
        for (int t = tid; t < IC_STEP * OC_TILE * 9; t += 256) {
            int icl = t / (OC_TILE * 9);
            int rem = t - icl * (OC_TILE * 9);
            int oc  = rem / 9;
            int k   = rem - oc * 9;
            sw[icl][oc][k] = cw[(((size_t)(ocbase + oc)) * IC_ + (ic0 + icl)) * 9 + k];
        }
        __syncthreads();

        #pragma unroll 1
        for (int icl = 0; icl < IC_STEP; icl++) {
            #pragma unroll
            for (int kh = 0; kh < 3; kh++) {
                #pragma unroll
                for (int kw = 0; kw < 3; kw++) {
                    const int k = kh * 3 + kw;
                    float wreg[OC_TILE];
                    #pragma unroll
                    for (int oc = 0; oc < OC_TILE; oc++) wreg[oc] = sw[icl][oc][k];
                    #pragma unroll
                    for (int p = 0; p < 4; p++) {
                        int h = th0 + 8 * p;
                        float xv = sx[icl][(h + kh) * 34 + (tw + kw)];
                        #pragma unroll
                        for (int oc = 0; oc < OC_TILE; oc++)
                            acc[p][oc] = fmaf(xv, wreg[oc], acc[p][oc]);
                    }
                }
            }
        }
    }

    // epilogue: demodulate + store
    #pragma unroll
    for (int oc = 0; oc < OC_TILE; oc++) {
        float dd = g_d[b * OC_ + ocbase + oc];
        #pragma unroll
        for (int p = 0; p < 4; p++) {
            int h = th0 + 8 * p;
            out[(((size_t)b * OC_ + ocbase + oc) * HW_ + h) * HW_ + tw] = acc[p][oc] * dd;
        }
    }
}

// ---------------------------------------------------------------------------
// Launch
// inputs: 0=x [16,512,32,32] f32, 1=style [16,512] f32, 2=aff_weight [512,512] f32,
//         3=aff_bias [512] f32, 4=conv_weight [512,512,3,3] f32
// out: [16,512,32,32] f32
// ---------------------------------------------------------------------------
extern "C" void kernel_launch(void* const* d_in, const int* in_sizes, int n_in,
                              void* d_out, int out_size) {
    const float* x    = (const float*)d_in[0];
    const float* sty  = (const float*)d_in[1];
    const float* affw = (const float*)d_in[2];
    const float* affb = (const float*)d_in[3];
    const float* cw   = (const float*)d_in[4];
    float* out = (float*)d_out;

    affine_kernel<<<B_, STYLE_>>>(sty, affw, affb);
    wsq_kernel<<<(OC_ * IC_ + 255) / 256, 256>>>(cw);
    demod_kernel<<<B_, OC_>>>();

    dim3 grid(OC_ / OC_TILE, B_);   // (32, 16)
    conv_kernel<<<grid, 256>>>(x, cw, out);
}

// round 3
// speedup vs baseline: 3.1613x; 3.1613x over previous
#include <cuda_runtime.h>
#include <cstdint>
#include <math.h>

// ---------------------------------------------------------------- constants
#define B_     16
#define IC_    512
#define OC_    512
#define HW_    32
#define STYLE_ 512
#define AFF_SCALE 0.04419417382415922f   // 1/sqrt(512)
#define W_SCALE   0.014731391274719739f  // 1/sqrt(512*9)

// ---------------------------------------------------------------- scratch
__device__ float g_s   [B_ * IC_];        // s' = (affine+1) * W_SCALE
__device__ float g_s2  [B_ * IC_];
__device__ float g_cw2t[IC_ * OC_];       // [i][o] = sum_k cw[o,i,k]^2
__device__ float g_d   [B_ * OC_];        // demod factors
__device__ float g_xs  [B_ * IC_ * HW_ * HW_];  // tf32-rounded x * s'
__device__ float g_wk  [9 * OC_ * IC_];         // tf32-rounded cw repacked [tap][o][i]

// ---------------------------------------------------------------- utils
__device__ __forceinline__ uint32_t smem_u32(const void* p) {
    uint32_t a;
    asm("{ .reg .u64 t; cvta.to.shared.u64 t, %1; cvt.u32.u64 %0, t; }" : "=r"(a) : "l"(p));
    return a;
}
__device__ __forceinline__ float to_tf32(float x) {
    float r;
    asm("cvt.rna.tf32.f32 %0, %1;" : "=f"(r) : "f"(x));
    return r;
}
#define CPA16(dst, src) \
    asm volatile("cp.async.ca.shared.global [%0], [%1], 16;" :: "r"(dst), "l"(src) : "memory")
#define CPA4Z(dst, src, sz) \
    asm volatile("cp.async.ca.shared.global [%0], [%1], 4, %2;" :: "r"(dst), "l"(src), "r"(sz) : "memory")
#define CPA_COMMIT() asm volatile("cp.async.commit_group;" ::: "memory")

// ---------------------------------------------------------------- prep kernels
__global__ void affine_kernel(const float* __restrict__ style,
                              const float* __restrict__ aff_w,
                              const float* __restrict__ aff_b) {
    int b = blockIdx.x, i = threadIdx.x;
    __shared__ float st[STYLE_];
    st[i] = style[b * STYLE_ + i];
    __syncthreads();
    const float* wrow = aff_w + (size_t)i * STYLE_;
    float acc = 0.f;
    #pragma unroll 8
    for (int j = 0; j < STYLE_; j++) acc = fmaf(wrow[j], st[j], acc);
    float sp = (acc * AFF_SCALE + aff_b[i] + 1.0f) * W_SCALE;
    g_s [b * IC_ + i] = sp;
    g_s2[b * IC_ + i] = sp * sp;
}

__global__ void wsq_kernel(const float* __restrict__ cw) {
    int idx = blockIdx.x * blockDim.x + threadIdx.x;
    if (idx >= OC_ * IC_) return;
    int o = idx / IC_, i = idx - o * IC_;
    const float* p = cw + (size_t)idx * 9;
    float a = 0.f;
    #pragma unroll
    for (int k = 0; k < 9; k++) a = fmaf(p[k], p[k], a);
    g_cw2t[i * OC_ + o] = a;
}

__global__ void demod_kernel() {
    int b = blockIdx.x, o = threadIdx.x;
    __shared__ float s2[IC_];
    s2[o] = g_s2[b * IC_ + o];
    __syncthreads();
    float a = 0.f;
    #pragma unroll 8
    for (int i = 0; i < IC_; i++) a = fmaf(s2[i], g_cw2t[i * OC_ + o], a);
    g_d[b * OC_ + o] = rsqrtf(a + 1e-8f);
}

__global__ void scale_x_kernel(const float* __restrict__ x) {
    int idx = blockIdx.x * blockDim.x + threadIdx.x;   // 16*512*1024
    int bi = idx >> 10;
    g_xs[idx] = to_tf32(x[idx] * g_s[bi]);
}

__global__ void repack_w_kernel(const float* __restrict__ cw) {
    int idx = blockIdx.x * blockDim.x + threadIdx.x;   // (k*OC+o)*IC+i
    int k = idx / (OC_ * IC_);
    int rem = idx - k * (OC_ * IC_);
    int o = rem / IC_, i = rem - o * IC_;
    g_wk[idx] = to_tf32(cw[((size_t)o * IC_ + i) * 9 + k]);
}

// ---------------------------------------------------------------- mma conv
// GEMM: M=512(oc) x N=16384(pixels) x K=4608 (16 ic-chunks x 9 taps x 32)
// CTA 128x128, 8 warps (2M x 4N), warp 64x32 via m16n8k8 tf32.
// smem (floats): A[2]: 128 rows x 36 stride; B[2]: 32 rows x 136 stride.
#define A_STRIDE 36
#define B_STRIDE 136
#define A_FLOATS (128 * A_STRIDE)   // 4608
#define B_FLOATS (32 * B_STRIDE)    // 4352
#define SMEM_FLOATS (2 * (A_FLOATS + B_FLOATS))  // 17920 -> 71680 B
#define NITER 144

__device__ __forceinline__ void stage_tiles(int it, uint32_t aA, uint32_t aB,
                                            int ocbase, int b, int h0, int tid) {
    const int chunk = it / 9;
    const int tap   = it - chunk * 9;
    const int ic0   = chunk * 32;
    // A: weights [128 oc][32 ic], 16B cp.async x4 per thread
    #pragma unroll
    for (int q = 0; q < 4; q++) {
        int id  = q * 256 + tid;
        int row = id >> 3, seg = id & 7;
        const float* src = g_wk + ((size_t)tap * OC_ + ocbase + row) * IC_ + ic0 + seg * 4;
        CPA16(aA + (uint32_t)(row * A_STRIDE + seg * 4) * 4, src);
    }
    // B: x [32 ic][128 pixels], 4B cp.async x16 per thread, zero-fill OOB
    const int dh = tap / 3 - 1, dw = tap - (tap / 3) * 3 - 1;
    #pragma unroll
    for (int q = 0; q < 16; q++) {
        int e   = q * 256 + tid;
        int icl = e >> 7, pix = e & 127;
        int pr  = pix >> 5, pc = pix & 31;
        int hh  = h0 + pr + dh, ww = pc + dw;
        bool ok = ((unsigned)hh < 32u) & ((unsigned)ww < 32u);
        const float* src = g_xs +
            (ok ? (((size_t)(b * IC_ + ic0 + icl)) * 32 + hh) * 32 + ww : 0);
        CPA4Z(aB + (uint32_t)(icl * B_STRIDE + pix) * 4, src, ok ? 4u : 0u);
    }
}

__global__ __launch_bounds__(256, 2)
void conv_mma(float* __restrict__ out) {
    extern __shared__ float sm[];
    float* As[2] = { sm,                        sm + A_FLOATS };
    float* Bs[2] = { sm + 2 * A_FLOATS,         sm + 2 * A_FLOATS + B_FLOATS };
    const uint32_t aA[2] = { smem_u32(As[0]), smem_u32(As[1]) };
    const uint32_t aB[2] = { smem_u32(Bs[0]), smem_u32(Bs[1]) };

    const int tid  = threadIdx.x;
    const int wid  = tid >> 5, lane = tid & 31;
    const int g    = lane >> 2, tg = lane & 3;
    const int m_w  = (wid >> 2) * 64;       // warp M offset
    const int n_w  = (wid & 3) * 32;        // warp N offset

    const int ocbase = blockIdx.x * 128;
    const int b  = blockIdx.y >> 3;
    const int h0 = (blockIdx.y & 7) * 4;

    float acc[4][4][4];
    #pragma unroll
    for (int mi = 0; mi < 4; mi++)
        #pragma unroll
        for (int ni = 0; ni < 4; ni++)
            #pragma unroll
            for (int c = 0; c < 4; c++) acc[mi][ni][c] = 0.f;

    stage_tiles(0, aA[0], aB[0], ocbase, b, h0, tid);
    CPA_COMMIT();

    #pragma unroll 1
    for (int it = 0; it < NITER; it++) {
        const int s = it & 1;
        if (it + 1 < NITER) {
            stage_tiles(it + 1, aA[s ^ 1], aB[s ^ 1], ocbase, b, h0, tid);
            CPA_COMMIT();
            asm volatile("cp.async.wait_group 1;" ::: "memory");
        } else {
            asm volatile("cp.async.wait_group 0;" ::: "memory");
        }
        __syncthreads();

        const float* A = As[s];
        const float* Bt = Bs[s];
        #pragma unroll
        for (int ks = 0; ks < 4; ks++) {
            const int k0 = ks * 8;
            uint32_t af[4][4], bf[4][2];
            #pragma unroll
            for (int mi = 0; mi < 4; mi++) {
                const float* pa = A + (m_w + mi * 16 + g) * A_STRIDE + k0 + tg;
                af[mi][0] = __float_as_uint(pa[0]);
                af[mi][1] = __float_as_uint(pa[8 * A_STRIDE]);
                af[mi][2] = __float_as_uint(pa[4]);
                af[mi][3] = __float_as_uint(pa[8 * A_STRIDE + 4]);
            }
            #pragma unroll
            for (int ni = 0; ni < 4; ni++) {
                const float* pb = Bt + (k0 + tg) * B_STRIDE + n_w + ni * 8 + g;
                bf[ni][0] = __float_as_uint(pb[0]);
                bf[ni][1] = __float_as_uint(pb[4 * B_STRIDE]);
            }
            #pragma unroll
            for (int mi = 0; mi < 4; mi++)
                #pragma unroll
                for (int ni = 0; ni < 4; ni++) {
                    asm volatile(
                        "mma.sync.aligned.m16n8k8.row.col.f32.tf32.tf32.f32 "
                        "{%0,%1,%2,%3}, {%4,%5,%6,%7}, {%8,%9}, {%0,%1,%2,%3};"
                        : "+f"(acc[mi][ni][0]), "+f"(acc[mi][ni][1]),
                          "+f"(acc[mi][ni][2]), "+f"(acc[mi][ni][3])
                        : "r"(af[mi][0]), "r"(af[mi][1]), "r"(af[mi][2]), "r"(af[mi][3]),
                          "r"(bf[ni][0]), "r"(bf[ni][1]));
                }
        }
        __syncthreads();
    }

    // ---- epilogue: demodulate + store
    #pragma unroll
    for (int mi = 0; mi < 4; mi++) {
        const int r0 = m_w + mi * 16 + g;
        const float d0 = g_d[b * OC_ + ocbase + r0];
        const float d1 = g_d[b * OC_ + ocbase + r0 + 8];
        #pragma unroll
        for (int ni = 0; ni < 4; ni++) {
            const int col = n_w + ni * 8 + 2 * tg;
            const int h = h0 + (col >> 5), w = col & 31;
            float2* p0 = (float2*)(out + (((size_t)(b * OC_ + ocbase + r0)) * 32 + h) * 32 + w);
            float2* p1 = (float2*)(out + (((size_t)(b * OC_ + ocbase + r0 + 8)) * 32 + h) * 32 + w);
            float2 v0 = { acc[mi][ni][0] * d0, acc[mi][ni][1] * d0 };
            float2 v1 = { acc[mi][ni][2] * d1, acc[mi][ni][3] * d1 };
            *p0 = v0;
            *p1 = v1;
        }
    }
}

// ---------------------------------------------------------------- launch
extern "C" void kernel_launch(void* const* d_in, const int* in_sizes, int n_in,
                              void* d_out, int out_size) {
    const float* x    = (const float*)d_in[0];
    const float* sty  = (const float*)d_in[1];
    const float* affw = (const float*)d_in[2];
    const float* affb = (const float*)d_in[3];
    const float* cw   = (const float*)d_in[4];
    float* out = (float*)d_out;

    affine_kernel<<<B_, STYLE_>>>(sty, affw, affb);
    wsq_kernel<<<(OC_ * IC_ + 255) / 256, 256>>>(cw);
    demod_kernel<<<B_, OC_>>>();
    scale_x_kernel<<<(B_ * IC_ * HW_ * HW_) / 256, 256>>>(x);
    repack_w_kernel<<<(9 * OC_ * IC_) / 256, 256>>>(cw);

    cudaFuncSetAttribute(conv_mma, cudaFuncAttributeMaxDynamicSharedMemorySize,
                         SMEM_FLOATS * 4);
    dim3 grid(4, 128);
    conv_mma<<<grid, 256, SMEM_FLOATS * 4>>>(out);
}

// round 4
// speedup vs baseline: 3.7735x; 1.1936x over previous
#include <cuda_runtime.h>
#include <cstdint>
#include <math.h>

// ---------------------------------------------------------------- constants
#define B_     16
#define IC_    512
#define OC_    512
#define HW_    32
#define STYLE_ 512
#define AFF_SCALE 0.04419417382415922f   // 1/sqrt(512)
#define W_SCALE   0.014731391274719739f  // 1/sqrt(512*9)

// ---------------------------------------------------------------- scratch
__device__ float g_s   [B_ * IC_];
__device__ float g_s2  [B_ * IC_];
__device__ float g_cw2t[IC_ * OC_];
__device__ float g_d   [B_ * OC_];
__device__ float g_xs  [B_ * IC_ * HW_ * HW_];   // tf32(x * s')
__device__ float g_wk  [9 * OC_ * IC_];          // tf32(cw) repacked [tap][o][i]

// ---------------------------------------------------------------- utils
__device__ __forceinline__ uint32_t smem_u32(const void* p) {
    uint32_t a;
    asm("{ .reg .u64 t; cvta.to.shared.u64 t, %1; cvt.u32.u64 %0, t; }" : "=r"(a) : "l"(p));
    return a;
}
__device__ __forceinline__ float to_tf32(float x) {
    float r;
    asm("cvt.rna.tf32.f32 %0, %1;" : "=f"(r) : "f"(x));
    return r;
}
#define CPA16(dst, src) \
    asm volatile("cp.async.ca.shared.global [%0], [%1], 16;" :: "r"(dst), "l"(src) : "memory")
#define CPA4Z(dst, src, sz) \
    asm volatile("cp.async.ca.shared.global [%0], [%1], 4, %2;" :: "r"(dst), "l"(src), "r"(sz) : "memory")
#define CPA_COMMIT() asm volatile("cp.async.commit_group;" ::: "memory")

// ---------------------------------------------------------------- prep kernels
__global__ void affine_kernel(const float* __restrict__ style,
                              const float* __restrict__ aff_w,
                              const float* __restrict__ aff_b) {
    int b = blockIdx.x, i = threadIdx.x;
    __shared__ float st[STYLE_];
    st[i] = style[b * STYLE_ + i];
    __syncthreads();
    const float* wrow = aff_w + (size_t)i * STYLE_;
    float acc = 0.f;
    #pragma unroll 8
    for (int j = 0; j < STYLE_; j++) acc = fmaf(wrow[j], st[j], acc);
    float sp = (acc * AFF_SCALE + aff_b[i] + 1.0f) * W_SCALE;
    g_s [b * IC_ + i] = sp;
    g_s2[b * IC_ + i] = sp * sp;
}

__global__ void wsq_kernel(const float* __restrict__ cw) {
    int idx = blockIdx.x * blockDim.x + threadIdx.x;
    if (idx >= OC_ * IC_) return;
    int o = idx / IC_, i = idx - o * IC_;
    const float* p = cw + (size_t)idx * 9;
    float a = 0.f;
    #pragma unroll
    for (int k = 0; k < 9; k++) a = fmaf(p[k], p[k], a);
    g_cw2t[i * OC_ + o] = a;
}

__global__ void demod_kernel() {
    int b = blockIdx.x, o = threadIdx.x;
    __shared__ float s2[IC_];
    s2[o] = g_s2[b * IC_ + o];
    __syncthreads();
    float a = 0.f;
    #pragma unroll 8
    for (int i = 0; i < IC_; i++) a = fmaf(s2[i], g_cw2t[i * OC_ + o], a);
    g_d[b * OC_ + o] = rsqrtf(a + 1e-8f);
}

__global__ void scale_x_kernel(const float* __restrict__ x) {
    int idx = blockIdx.x * blockDim.x + threadIdx.x;   // over float4s: 16*512*256
    int bi = idx >> 8;
    float s = g_s[bi];
    const float4 v = ((const float4*)x)[idx];
    float4 r;
    r.x = to_tf32(v.x * s); r.y = to_tf32(v.y * s);
    r.z = to_tf32(v.z * s); r.w = to_tf32(v.w * s);
    ((float4*)g_xs)[idx] = r;
}

__global__ void repack_w_kernel(const float* __restrict__ cw) {
    int idx = blockIdx.x * blockDim.x + threadIdx.x;   // (k*OC+o)*IC+i
    int k = idx / (OC_ * IC_);
    int rem = idx - k * (OC_ * IC_);
    int o = rem / IC_, i = rem - o * IC_;
    g_wk[idx] = to_tf32(cw[((size_t)o * IC_ + i) * 9 + k]);
}

// ---------------------------------------------------------------- mma conv
// GEMM: M=512(oc) x N=16384(pix) x K=4608. CTA 128x128, 4 warps (2x2), warp 64x64.
// 3-stage cp.async pipeline, one __syncthreads per iter.
#define A_ST 36
#define B_ST 136
#define A_FL (128 * A_ST)            // 4608 floats
#define B_FL (32 * B_ST)             // 4352 floats
#define STG_FL (A_FL + B_FL)         // 8960 floats per stage
#define SMEM_BYTES (3 * STG_FL * 4)  // 107520
#define NITER 144

__device__ __forceinline__ void stage_tiles(int it, uint32_t aA, uint32_t aB,
                                            int ocbase, int b, int h0, int tid) {
    const int chunk = it / 9;
    const int tap   = it - chunk * 9;
    const int ic0   = chunk * 32;
    // A: [128 oc][32 ic], 8 x 16B per thread (lanes 0-7 cover one row -> CF)
    #pragma unroll
    for (int q = 0; q < 8; q++) {
        int id  = q * 128 + tid;
        int row = id >> 3, seg = id & 7;
        const float* src = g_wk + ((size_t)tap * OC_ + ocbase + row) * IC_ + ic0 + seg * 4;
        CPA16(aA + (uint32_t)(row * A_ST + seg * 4) * 4, src);
    }
    // B: [32 ic][128 pix], 32 x 4B per thread, zero-fill OOB (lanes: same ic, pix++)
    const int dh = tap / 3 - 1, dw = tap - (tap / 3) * 3 - 1;
    #pragma unroll
    for (int q = 0; q < 32; q++) {
        int e   = q * 128 + tid;
        int icl = e >> 7, pix = e & 127;
        int hh  = h0 + (pix >> 5) + dh, ww = (pix & 31) + dw;
        bool ok = ((unsigned)hh < 32u) & ((unsigned)ww < 32u);
        const float* src = g_xs +
            (ok ? (((size_t)(b * IC_ + ic0 + icl)) * 32 + hh) * 32 + ww : 0);
        CPA4Z(aB + (uint32_t)(icl * B_ST + pix) * 4, src, ok ? 4u : 0u);
    }
}

__global__ __launch_bounds__(128, 2)
void conv_mma(float* __restrict__ out) {
    extern __shared__ float sm[];
    const uint32_t sb = smem_u32(sm);

    const int tid  = threadIdx.x;
    const int wid  = tid >> 5, lane = tid & 31;
    const int g    = lane >> 2, tg = lane & 3;
    const int m_w  = (wid >> 1) * 64;        // warp M offset (0,64)
    const int n_w  = (wid & 1) * 64;         // warp N offset (0,64)

    const int ocbase = blockIdx.x * 128;
    const int b  = blockIdx.y >> 3;
    const int h0 = (blockIdx.y & 7) * 4;

    float acc[4][8][4];
    #pragma unroll
    for (int mi = 0; mi < 4; mi++)
        #pragma unroll
        for (int ni = 0; ni < 8; ni++)
            #pragma unroll
            for (int c = 0; c < 4; c++) acc[mi][ni][c] = 0.f;

    // prologue: stages 0,1
    stage_tiles(0, sb, sb + A_FL * 4, ocbase, b, h0, tid);
    CPA_COMMIT();
    stage_tiles(1, sb + STG_FL * 4, sb + (STG_FL + A_FL) * 4, ocbase, b, h0, tid);
    CPA_COMMIT();

    int slot = 0;
    #pragma unroll 1
    for (int it = 0; it < NITER; it++) {
        asm volatile("cp.async.wait_group 1;" ::: "memory");
        __syncthreads();

        // stage it+2 (overlaps with compute below)
        if (it + 2 < NITER) {
            int s2 = slot + 2; if (s2 >= 3) s2 -= 3;
            stage_tiles(it + 2, sb + s2 * STG_FL * 4, sb + (s2 * STG_FL + A_FL) * 4,
                        ocbase, b, h0, tid);
        }
        CPA_COMMIT();

        const float* A  = sm + slot * STG_FL;
        const float* Bt = A + A_FL;

        #pragma unroll
        for (int ks = 0; ks < 4; ks++) {
            const int k0 = ks * 8;
            uint32_t af[4][4], bf[8][2];
            #pragma unroll
            for (int mi = 0; mi < 4; mi++) {
                const float* pa = A + (m_w + mi * 16 + g) * A_ST + k0 + tg;
                af[mi][0] = __float_as_uint(pa[0]);
                af[mi][1] = __float_as_uint(pa[8 * A_ST]);
                af[mi][2] = __float_as_uint(pa[4]);
                af[mi][3] = __float_as_uint(pa[8 * A_ST + 4]);
            }
            #pragma unroll
            for (int ni = 0; ni < 8; ni++) {
                const float* pb = Bt + (k0 + tg) * B_ST + n_w + ni * 8 + g;
                bf[ni][0] = __float_as_uint(pb[0]);
                bf[ni][1] = __float_as_uint(pb[4 * B_ST]);
            }
            #pragma unroll
            for (int mi = 0; mi < 4; mi++)
                #pragma unroll
                for (int ni = 0; ni < 8; ni++) {
                    asm volatile(
                        "mma.sync.aligned.m16n8k8.row.col.f32.tf32.tf32.f32 "
                        "{%0,%1,%2,%3}, {%4,%5,%6,%7}, {%8,%9}, {%0,%1,%2,%3};"
                        : "+f"(acc[mi][ni][0]), "+f"(acc[mi][ni][1]),
                          "+f"(acc[mi][ni][2]), "+f"(acc[mi][ni][3])
                        : "r"(af[mi][0]), "r"(af[mi][1]), "r"(af[mi][2]), "r"(af[mi][3]),
                          "r"(bf[ni][0]), "r"(bf[ni][1]));
                }
        }
        slot++; if (slot == 3) slot = 0;
    }

    // ---- epilogue: demodulate + store
    #pragma unroll
    for (int mi = 0; mi < 4; mi++) {
        const int r0 = m_w + mi * 16 + g;
        const float d0 = g_d[b * OC_ + ocbase + r0];
        const float d1 = g_d[b * OC_ + ocbase + r0 + 8];
        #pragma unroll
        for (int ni = 0; ni < 8; ni++) {
            const int col = n_w + ni * 8 + 2 * tg;
            const int h = h0 + (col >> 5), w = col & 31;
            float2* p0 = (float2*)(out + (((size_t)(b * OC_ + ocbase + r0)) * 32 + h) * 32 + w);
            float2* p1 = (float2*)(out + (((size_t)(b * OC_ + ocbase + r0 + 8)) * 32 + h) * 32 + w);
            float2 v0 = { acc[mi][ni][0] * d0, acc[mi][ni][1] * d0 };
            float2 v1 = { acc[mi][ni][2] * d1, acc[mi][ni][3] * d1 };
            *p0 = v0;
            *p1 = v1;
        }
    }
}

// ---------------------------------------------------------------- launch
extern "C" void kernel_launch(void* const* d_in, const int* in_sizes, int n_in,
                              void* d_out, int out_size) {
    const float* x    = (const float*)d_in[0];
    const float* sty  = (const float*)d_in[1];
    const float* affw = (const float*)d_in[2];
    const float* affb = (const float*)d_in[3];
    const float* cw   = (const float*)d_in[4];
    float* out = (float*)d_out;

    affine_kernel<<<B_, STYLE_>>>(sty, affw, affb);
    wsq_kernel<<<(OC_ * IC_ + 255) / 256, 256>>>(cw);
    demod_kernel<<<B_, OC_>>>();
    scale_x_kernel<<<(B_ * IC_ * HW_ * HW_ / 4) / 256, 256>>>(x);
    repack_w_kernel<<<(9 * OC_ * IC_) / 256, 256>>>(cw);

    cudaFuncSetAttribute(conv_mma, cudaFuncAttributeMaxDynamicSharedMemorySize, SMEM_BYTES);
    dim3 grid(4, 128);
    conv_mma<<<grid, 128, SMEM_BYTES>>>(out);
}

// round 5
// speedup vs baseline: 6.4976x; 1.7219x over previous
#include <cuda_runtime.h>
#include <cuda_fp16.h>
#include <cstdint>
#include <math.h>

// ---------------------------------------------------------------- constants
#define B_     16
#define IC_    512
#define OC_    512
#define HW_    32
#define STYLE_ 512
#define AFF_SCALE 0.04419417382415922f   // 1/sqrt(512)
#define W_SCALE   0.014731391274719739f  // 1/sqrt(512*9)

// ---------------------------------------------------------------- scratch
__device__ float g_s   [B_ * IC_];
__device__ float g_s2  [B_ * IC_];
__device__ float g_cw2t[IC_ * OC_];
__device__ float g_d   [B_ * OC_];
__device__ __half g_xt [B_ * HW_ * HW_ * IC_];   // half(x*s'), layout [b][h][w][ic]
__device__ __half g_wk [9 * OC_ * IC_];          // half(cw), layout [tap][o][i]

// ---------------------------------------------------------------- utils
__device__ __forceinline__ uint32_t smem_u32(const void* p) {
    uint32_t a;
    asm("{ .reg .u64 t; cvta.to.shared.u64 t, %1; cvt.u32.u64 %0, t; }" : "=r"(a) : "l"(p));
    return a;
}
#define CPA16(dst, src) \
    asm volatile("cp.async.ca.shared.global [%0], [%1], 16;" :: "r"(dst), "l"(src) : "memory")
#define CPA16Z(dst, src, sz) \
    asm volatile("cp.async.ca.shared.global [%0], [%1], 16, %2;" :: "r"(dst), "l"(src), "r"(sz) : "memory")
#define CPA_COMMIT() asm volatile("cp.async.commit_group;" ::: "memory")

// ---------------------------------------------------------------- prep kernels
__global__ void affine_kernel(const float* __restrict__ style,
                              const float* __restrict__ aff_w,
                              const float* __restrict__ aff_b) {
    int b = blockIdx.x, i = threadIdx.x;
    __shared__ float st[STYLE_];
    st[i] = style[b * STYLE_ + i];
    __syncthreads();
    const float* wrow = aff_w + (size_t)i * STYLE_;
    float acc = 0.f;
    #pragma unroll 8
    for (int j = 0; j < STYLE_; j++) acc = fmaf(wrow[j], st[j], acc);
    float sp = (acc * AFF_SCALE + aff_b[i] + 1.0f) * W_SCALE;
    g_s [b * IC_ + i] = sp;
    g_s2[b * IC_ + i] = sp * sp;
}

__global__ void wsq_kernel(const float* __restrict__ cw) {
    int idx = blockIdx.x * blockDim.x + threadIdx.x;
    if (idx >= OC_ * IC_) return;
    int o = idx / IC_, i = idx - o * IC_;
    const float* p = cw + (size_t)idx * 9;
    float a = 0.f;
    #pragma unroll
    for (int k = 0; k < 9; k++) a = fmaf(p[k], p[k], a);
    g_cw2t[i * OC_ + o] = a;
}

__global__ void demod_kernel() {
    int b = blockIdx.x, o = threadIdx.x;
    __shared__ float s2[IC_];
    s2[o] = g_s2[b * IC_ + o];
    __syncthreads();
    float a = 0.f;
    #pragma unroll 8
    for (int i = 0; i < IC_; i++) a = fmaf(s2[i], g_cw2t[i * OC_ + o], a);
    g_d[b * OC_ + o] = rsqrtf(a + 1e-8f);
}

// scale by style, convert to half, transpose to [b][pix][ic]
// grid (B_*16, 8), block 256: tile = 32 ic x 128 pix
__global__ void scale_xt_kernel(const float* __restrict__ x) {
    __shared__ float t[32][133];
    const int b   = blockIdx.x >> 4;
    const int ic0 = (blockIdx.x & 15) * 32;
    const int p0  = blockIdx.y * 128;
    const int tid = threadIdx.x;

    #pragma unroll
    for (int e = 0; e < 16; e++) {
        int idx = e * 256 + tid;
        int icl = idx >> 7, pix = idx & 127;
        t[icl][pix] = x[((size_t)(b * IC_ + ic0 + icl)) * 1024 + p0 + pix]
                      * g_s[b * IC_ + ic0 + icl];
    }
    __syncthreads();
    #pragma unroll
    for (int e = 0; e < 16; e++) {
        int idx = e * 256 + tid;
        int pixl = idx >> 5, icw = idx & 31;
        g_xt[((size_t)(b * 1024 + p0 + pixl)) * IC_ + ic0 + icw] =
            __float2half_rn(t[icw][pixl]);
    }
}

__global__ void repack_w_kernel(const float* __restrict__ cw) {
    int idx = blockIdx.x * blockDim.x + threadIdx.x;   // (k*OC+o)*IC+i
    int k = idx / (OC_ * IC_);
    int rem = idx - k * (OC_ * IC_);
    int o = rem / IC_, i = rem - o * IC_;
    g_wk[idx] = __float2half_rn(cw[((size_t)o * IC_ + i) * 9 + k]);
}

// ---------------------------------------------------------------- fp16 mma conv
// GEMM M=512(oc) x N=16384(pix) x K=4608.  CTA 128x128, 4 warps (2x2), warp 64x64.
// A smem [128 oc][40h pitch], B smem [128 pix][40h pitch] (k-contiguous rows).
// m16n8k16.f16.f16.f32; 3-stage cp.async pipeline, 1 sync/iter.
#define PITCH_H 40
#define A_BYTES (128 * PITCH_H * 2)   // 10240
#define B_BYTES (128 * PITCH_H * 2)   // 10240
#define STG_BYTES (A_BYTES + B_BYTES) // 20480
#define SMEM_BYTES (3 * STG_BYTES)    // 61440
#define NITER 144

__device__ __forceinline__ void stage_tiles(int it, uint32_t aA, uint32_t aB,
                                            int ocbase, int b, int h0, int tid) {
    const int chunk = it / 9;
    const int tap   = it - chunk * 9;
    const int ic0   = chunk * 32;
    // A: 128 rows x 32 halves (64B) -> 4 x 16B chunks/row; 512 chunks / 128 thr
    #pragma unroll
    for (int q = 0; q < 4; q++) {
        int idx = q * 128 + tid;
        int row = idx >> 2, seg = idx & 3;
        const __half* src = g_wk + ((size_t)tap * OC_ + ocbase + row) * IC_ + ic0 + seg * 8;
        CPA16(aA + (uint32_t)(row * PITCH_H + seg * 8) * 2, src);
    }
    // B: 128 pixel rows x 32 halves; zero-fill OOB rows
    const int dh = tap / 3 - 1, dw = tap - (tap / 3) * 3 - 1;
    #pragma unroll
    for (int q = 0; q < 4; q++) {
        int idx = q * 128 + tid;
        int pix = idx >> 2, seg = idx & 3;
        int hh  = h0 + (pix >> 5) + dh, ww = (pix & 31) + dw;
        bool ok = ((unsigned)hh < 32u) & ((unsigned)ww < 32u);
        const __half* src = g_xt +
            (ok ? ((size_t)(b * 1024 + hh * 32 + ww)) * IC_ + ic0 + seg * 8 : 0);
        CPA16Z(aB + (uint32_t)(pix * PITCH_H + seg * 8) * 2, src, ok ? 16u : 0u);
    }
}

__global__ __launch_bounds__(128, 2)
void conv_mma(float* __restrict__ out) {
    extern __shared__ __half sm[];
    const uint32_t sb = smem_u32(sm);

    const int tid  = threadIdx.x;
    const int wid  = tid >> 5, lane = tid & 31;
    const int g    = lane >> 2, tg = lane & 3;
    const int m_w  = (wid >> 1) * 64;
    const int n_w  = (wid & 1) * 64;

    const int ocbase = blockIdx.x * 128;
    const int b  = blockIdx.y >> 3;
    const int h0 = (blockIdx.y & 7) * 4;

    float acc[4][8][4];
    #pragma unroll
    for (int mi = 0; mi < 4; mi++)
        #pragma unroll
        for (int ni = 0; ni < 8; ni++)
            #pragma unroll
            for (int c = 0; c < 4; c++) acc[mi][ni][c] = 0.f;

    stage_tiles(0, sb, sb + A_BYTES, ocbase, b, h0, tid);
    CPA_COMMIT();
    stage_tiles(1, sb + STG_BYTES, sb + STG_BYTES + A_BYTES, ocbase, b, h0, tid);
    CPA_COMMIT();

    int slot = 0;
    #pragma unroll 1
    for (int it = 0; it < NITER; it++) {
        asm volatile("cp.async.wait_group 1;" ::: "memory");
        __syncthreads();

        if (it + 2 < NITER) {
            int s2 = slot + 2; if (s2 >= 3) s2 -= 3;
            stage_tiles(it + 2, sb + s2 * STG_BYTES, sb + s2 * STG_BYTES + A_BYTES,
                        ocbase, b, h0, tid);
        }
        CPA_COMMIT();

        const __half* A  = sm + slot * (STG_BYTES / 2);
        const __half* Bt = A + (A_BYTES / 2);

        #pragma unroll
        for (int ks = 0; ks < 2; ks++) {
            const int k0 = ks * 16;
            uint32_t af[4][4], bf[8][2];
            #pragma unroll
            for (int mi = 0; mi < 4; mi++) {
                const __half* pa = A + (m_w + mi * 16 + g) * PITCH_H + k0 + 2 * tg;
                af[mi][0] = *(const uint32_t*)(pa);
                af[mi][1] = *(const uint32_t*)(pa + 8 * PITCH_H);
                af[mi][2] = *(const uint32_t*)(pa + 8);
                af[mi][3] = *(const uint32_t*)(pa + 8 * PITCH_H + 8);
            }
            #pragma unroll
            for (int ni = 0; ni < 8; ni++) {
                const __half* pb = Bt + (n_w + ni * 8 + g) * PITCH_H + k0 + 2 * tg;
                bf[ni][0] = *(const uint32_t*)(pb);
                bf[ni][1] = *(const uint32_t*)(pb + 8);
            }
            #pragma unroll
            for (int mi = 0; mi < 4; mi++)
                #pragma unroll
                for (int ni = 0; ni < 8; ni++) {
                    asm volatile(
                        "mma.sync.aligned.m16n8k16.row.col.f32.f16.f16.f32 "
                        "{%0,%1,%2,%3}, {%4,%5,%6,%7}, {%8,%9}, {%0,%1,%2,%3};"
                        : "+f"(acc[mi][ni][0]), "+f"(acc[mi][ni][1]),
                          "+f"(acc[mi][ni][2]), "+f"(acc[mi][ni][3])
                        : "r"(af[mi][0]), "r"(af[mi][1]), "r"(af[mi][2]), "r"(af[mi][3]),
                          "r"(bf[ni][0]), "r"(bf[ni][1]));
                }
        }
        slot++; if (slot == 3) slot = 0;
    }

    // ---- epilogue: demodulate + store
    #pragma unroll
    for (int mi = 0; mi < 4; mi++) {
        const int r0 = m_w + mi * 16 + g;
        const float d0 = g_d[b * OC_ + ocbase + r0];
        const float d1 = g_d[b * OC_ + ocbase + r0 + 8];
        #pragma unroll
        for (int ni = 0; ni < 8; ni++) {
            const int col = n_w + ni * 8 + 2 * tg;
            const int h = h0 + (col >> 5), w = col & 31;
            float2* p0 = (float2*)(out + (((size_t)(b * OC_ + ocbase + r0)) * 32 + h) * 32 + w);
            float2* p1 = (float2*)(out + (((size_t)(b * OC_ + ocbase + r0 + 8)) * 32 + h) * 32 + w);
            float2 v0 = { acc[mi][ni][0] * d0, acc[mi][ni][1] * d0 };
            float2 v1 = { acc[mi][ni][2] * d1, acc[mi][ni][3] * d1 };
            *p0 = v0;
            *p1 = v1;
        }
    }
}

// ---------------------------------------------------------------- launch
extern "C" void kernel_launch(void* const* d_in, const int* in_sizes, int n_in,
                              void* d_out, int out_size) {
    const float* x    = (const float*)d_in[0];
    const float* sty  = (const float*)d_in[1];
    const float* affw = (const float*)d_in[2];
    const float* affb = (const float*)d_in[3];
    const float* cw   = (const float*)d_in[4];
    float* out = (float*)d_out;

    affine_kernel<<<B_, STYLE_>>>(sty, affw, affb);
    wsq_kernel<<<(OC_ * IC_ + 255) / 256, 256>>>(cw);
    demod_kernel<<<B_, OC_>>>();
    {
        dim3 g(B_ * 16, 8);
        scale_xt_kernel<<<g, 256>>>(x);
    }
    repack_w_kernel<<<(9 * OC_ * IC_) / 256, 256>>>(cw);

    cudaFuncSetAttribute(conv_mma, cudaFuncAttributeMaxDynamicSharedMemorySize, SMEM_BYTES);
    dim3 grid(4, 128);
    conv_mma<<<grid, 128, SMEM_BYTES>>>(out);
}

// round 6
// speedup vs baseline: 7.0845x; 1.0903x over previous
#include <cuda_runtime.h>
#include <cuda_fp16.h>
#include <cstdint>
#include <math.h>

// ---------------------------------------------------------------- constants
#define B_     16
#define IC_    512
#define OC_    512
#define HW_    32
#define STYLE_ 512
#define AFF_SCALE 0.04419417382415922f   // 1/sqrt(512)
#define W_SCALE   0.014731391274719739f  // 1/sqrt(512*9)

// ---------------------------------------------------------------- scratch
__device__ float g_s   [B_ * IC_];
__device__ float g_s2  [B_ * IC_];
__device__ float g_cw2t[IC_ * OC_];
__device__ float g_d   [B_ * OC_];
__device__ __half g_xt [B_ * HW_ * HW_ * IC_];   // half(x*s'), layout [b][pix][ic]
__device__ __half g_wk [9 * OC_ * IC_];          // half(cw), layout [tap][o][i]

// ---------------------------------------------------------------- utils
__device__ __forceinline__ uint32_t smem_u32(const void* p) {
    uint32_t a;
    asm("{ .reg .u64 t; cvta.to.shared.u64 t, %1; cvt.u32.u64 %0, t; }" : "=r"(a) : "l"(p));
    return a;
}
#define CPA16(dst, src) \
    asm volatile("cp.async.cg.shared.global [%0], [%1], 16;" :: "r"(dst), "l"(src) : "memory")
#define CPA16Z(dst, src, sz) \
    asm volatile("cp.async.cg.shared.global [%0], [%1], 16, %2;" :: "r"(dst), "l"(src), "r"(sz) : "memory")
#define CPA_COMMIT() asm volatile("cp.async.commit_group;" ::: "memory")
#define LDSM_X4(r0, r1, r2, r3, addr) \
    asm volatile("ldmatrix.sync.aligned.m8n8.x4.shared.b16 {%0,%1,%2,%3}, [%4];" \
                 : "=r"(r0), "=r"(r1), "=r"(r2), "=r"(r3) : "r"(addr))

// ---------------------------------------------------------------- prep kernels
__global__ void affine_kernel(const float* __restrict__ style,
                              const float* __restrict__ aff_w,
                              const float* __restrict__ aff_b) {
    int b = blockIdx.x, i = threadIdx.x;
    __shared__ float st[STYLE_];
    st[i] = style[b * STYLE_ + i];
    __syncthreads();
    const float* wrow = aff_w + (size_t)i * STYLE_;
    float acc = 0.f;
    #pragma unroll 8
    for (int j = 0; j < STYLE_; j++) acc = fmaf(wrow[j], st[j], acc);
    float sp = (acc * AFF_SCALE + aff_b[i] + 1.0f) * W_SCALE;
    g_s [b * IC_ + i] = sp;
    g_s2[b * IC_ + i] = sp * sp;
}

__global__ void wsq_kernel(const float* __restrict__ cw) {
    int idx = blockIdx.x * blockDim.x + threadIdx.x;
    if (idx >= OC_ * IC_) return;
    int o = idx / IC_, i = idx - o * IC_;
    const float* p = cw + (size_t)idx * 9;
    float a = 0.f;
    #pragma unroll
    for (int k = 0; k < 9; k++) a = fmaf(p[k], p[k], a);
    g_cw2t[i * OC_ + o] = a;
}

__global__ void demod_kernel() {
    int b = blockIdx.x, o = threadIdx.x;
    __shared__ float s2[IC_];
    s2[o] = g_s2[b * IC_ + o];
    __syncthreads();
    float a = 0.f;
    #pragma unroll 8
    for (int i = 0; i < IC_; i++) a = fmaf(s2[i], g_cw2t[i * OC_ + o], a);
    g_d[b * OC_ + o] = rsqrtf(a + 1e-8f);
}

// scale + half-convert + transpose to [b][pix][ic].
// grid (B_*8, 16), block 256: tile = 64 ic x 64 pix.
__global__ void scale_xt_kernel(const float* __restrict__ x) {
    __shared__ float t[64][65];
    const int b   = blockIdx.x >> 3;
    const int ic0 = (blockIdx.x & 7) * 64;
    const int p0  = blockIdx.y * 64;
    const int tid = threadIdx.x;

    // load: 64 rows x 16 float4 = 1024 float4, 4 per thread, coalesced
    #pragma unroll
    for (int e = 0; e < 4; e++) {
        int idx = e * 256 + tid;
        int row = idx >> 4, c4 = idx & 15;
        float4 v = *(const float4*)(x + ((size_t)(b * IC_ + ic0 + row)) * 1024 + p0 + c4 * 4);
        float s = g_s[b * IC_ + ic0 + row];
        t[row][c4 * 4 + 0] = v.x * s;
        t[row][c4 * 4 + 1] = v.y * s;
        t[row][c4 * 4 + 2] = v.z * s;
        t[row][c4 * 4 + 3] = v.w * s;
    }
    __syncthreads();
    // write: per warp one pixel row of 64 ic as 32 half2 (128B)
    #pragma unroll
    for (int e = 0; e < 8; e++) {
        int pixl = e * 8 + (tid >> 5);
        int icp  = tid & 31;
        __half2 v = __floats2half2_rn(t[2 * icp][pixl], t[2 * icp + 1][pixl]);
        *(__half2*)(g_xt + ((size_t)(b * 1024 + p0 + pixl)) * IC_ + ic0 + 2 * icp) = v;
    }
}

__global__ void repack_w_kernel(const float* __restrict__ cw) {
    int idx = blockIdx.x * blockDim.x + threadIdx.x;   // (k*OC+o)*IC+i
    int k = idx / (OC_ * IC_);
    int rem = idx - k * (OC_ * IC_);
    int o = rem / IC_, i = rem - o * IC_;
    g_wk[idx] = __float2half_rn(cw[((size_t)o * IC_ + i) * 9 + k]);
}

// ---------------------------------------------------------------- fp16 mma conv
// GEMM M=512(oc) x N=16384(pix) x K=4608. CTA 128x128, 4 warps (2x2), warp 64x64.
// A smem [128 oc][40h], B smem [128 pix][40h]; ldmatrix fragments;
// m16n8k16.f16.f16.f32; 3-stage cp.async pipeline, 1 sync/iter.
#define PITCH_H 40
#define A_BYTES (128 * PITCH_H * 2)
#define B_BYTES (128 * PITCH_H * 2)
#define STG_BYTES (A_BYTES + B_BYTES)
#define SMEM_BYTES (3 * STG_BYTES)    // 61440
#define NITER 144

__device__ __forceinline__ void stage_tiles(int it, uint32_t aA, uint32_t aB,
                                            int ocbase, int b, int h0, int tid) {
    const int chunk = it / 9;
    const int tap   = it - chunk * 9;
    const int ic0   = chunk * 32;
    #pragma unroll
    for (int q = 0; q < 4; q++) {
        int idx = q * 128 + tid;
        int row = idx >> 2, seg = idx & 3;
        const __half* src = g_wk + ((size_t)tap * OC_ + ocbase + row) * IC_ + ic0 + seg * 8;
        CPA16(aA + (uint32_t)(row * PITCH_H + seg * 8) * 2, src);
    }
    const int dh = tap / 3 - 1, dw = tap - (tap / 3) * 3 - 1;
    #pragma unroll
    for (int q = 0; q < 4; q++) {
        int idx = q * 128 + tid;
        int pix = idx >> 2, seg = idx & 3;
        int hh  = h0 + (pix >> 5) + dh, ww = (pix & 31) + dw;
        bool ok = ((unsigned)hh < 32u) & ((unsigned)ww < 32u);
        const __half* src = g_xt +
            (ok ? ((size_t)(b * 1024 + hh * 32 + ww)) * IC_ + ic0 + seg * 8 : 0);
        CPA16Z(aB + (uint32_t)(pix * PITCH_H + seg * 8) * 2, src, ok ? 16u : 0u);
    }
}

__global__ __launch_bounds__(128, 2)
void conv_mma(float* __restrict__ out) {
    extern __shared__ __half sm[];
    const uint32_t sb = smem_u32(sm);

    const int tid  = threadIdx.x;
    const int wid  = tid >> 5, lane = tid & 31;
    const int g    = lane >> 2, tg = lane & 3;
    const int m_w  = (wid >> 1) * 64;
    const int n_w  = (wid & 1) * 64;

    const int ocbase = blockIdx.x * 128;
    const int b  = blockIdx.y >> 3;
    const int h0 = (blockIdx.y & 7) * 4;

    // ldmatrix lane-role precompute
    const int aRow = m_w + ((lane >> 3) & 1) * 8 + (lane & 7);  // tiles 0,1 -> m, m+8
    const int aK   = (lane >> 4) * 8;                           // tiles 2,3 -> k+8
    const int bRow = n_w + ((lane >> 4) ? 8 : 0) + (lane & 7);  // tiles 2,3 -> n+8
    const int bK   = ((lane >> 3) & 1) * 8;                     // tiles 1,3 -> k+8

    float acc[4][8][4];
    #pragma unroll
    for (int mi = 0; mi < 4; mi++)
        #pragma unroll
        for (int ni = 0; ni < 8; ni++)
            #pragma unroll
            for (int c = 0; c < 4; c++) acc[mi][ni][c] = 0.f;

    stage_tiles(0, sb, sb + A_BYTES, ocbase, b, h0, tid);
    CPA_COMMIT();
    stage_tiles(1, sb + STG_BYTES, sb + STG_BYTES + A_BYTES, ocbase, b, h0, tid);
    CPA_COMMIT();

    int slot = 0;
    #pragma unroll 1
    for (int it = 0; it < NITER; it++) {
        asm volatile("cp.async.wait_group 1;" ::: "memory");
        __syncthreads();

        if (it + 2 < NITER) {
            int s2 = slot + 2; if (s2 >= 3) s2 -= 3;
            stage_tiles(it + 2, sb + s2 * STG_BYTES, sb + s2 * STG_BYTES + A_BYTES,
                        ocbase, b, h0, tid);
        }
        CPA_COMMIT();

        const uint32_t Ab = sb + slot * STG_BYTES;
        const uint32_t Bb = Ab + A_BYTES;

        #pragma unroll
        for (int ks = 0; ks < 2; ks++) {
            uint32_t af[4][4], bf[4][4];
            #pragma unroll
            for (int mi = 0; mi < 4; mi++) {
                uint32_t addr = Ab + (uint32_t)((aRow + mi * 16) * PITCH_H + aK + ks * 16) * 2;
                LDSM_X4(af[mi][0], af[mi][1], af[mi][2], af[mi][3], addr);
            }
            #pragma unroll
            for (int nj = 0; nj < 4; nj++) {
                uint32_t addr = Bb + (uint32_t)((bRow + nj * 16) * PITCH_H + bK + ks * 16) * 2;
                LDSM_X4(bf[nj][0], bf[nj][1], bf[nj][2], bf[nj][3], addr);
            }
            #pragma unroll
            for (int mi = 0; mi < 4; mi++)
                #pragma unroll
                for (int ni = 0; ni < 8; ni++) {
                    const uint32_t b0 = bf[ni >> 1][(ni & 1) * 2];
                    const uint32_t b1 = bf[ni >> 1][(ni & 1) * 2 + 1];
                    asm volatile(
                        "mma.sync.aligned.m16n8k16.row.col.f32.f16.f16.f32 "
                        "{%0,%1,%2,%3}, {%4,%5,%6,%7}, {%8,%9}, {%0,%1,%2,%3};"
                        : "+f"(acc[mi][ni][0]), "+f"(acc[mi][ni][1]),
                          "+f"(acc[mi][ni][2]), "+f"(acc[mi][ni][3])
                        : "r"(af[mi][0]), "r"(af[mi][1]), "r"(af[mi][2]), "r"(af[mi][3]),
                          "r"(b0), "r"(b1));
                }
        }
        slot++; if (slot == 3) slot = 0;
    }

    // ---- epilogue: demodulate + store
    #pragma unroll
    for (int mi = 0; mi < 4; mi++) {
        const int r0 = m_w + mi * 16 + g;
        const float d0 = g_d[b * OC_ + ocbase + r0];
        const float d1 = g_d[b * OC_ + ocbase + r0 + 8];
        #pragma unroll
        for (int ni = 0; ni < 8; ni++) {
            const int col = n_w + ni * 8 + 2 * tg;
            const int h = h0 + (col >> 5), w = col & 31;
            float2* p0 = (float2*)(out + (((size_t)(b * OC_ + ocbase + r0)) * 32 + h) * 32 + w);
            float2* p1 = (float2*)(out + (((size_t)(b * OC_ + ocbase + r0 + 8)) * 32 + h) * 32 + w);
            float2 v0 = { acc[mi][ni][0] * d0, acc[mi][ni][1] * d0 };
            float2 v1 = { acc[mi][ni][2] * d1, acc[mi][ni][3] * d1 };
            *p0 = v0;
            *p1 = v1;
        }
    }
}

// ---------------------------------------------------------------- launch
extern "C" void kernel_launch(void* const* d_in, const int* in_sizes, int n_in,
                              void* d_out, int out_size) {
    const float* x    = (const float*)d_in[0];
    const float* sty  = (const float*)d_in[1];
    const float* affw = (const float*)d_in[2];
    const float* affb = (const float*)d_in[3];
    const float* cw   = (const float*)d_in[4];
    float* out = (float*)d_out;

    affine_kernel<<<B_, STYLE_>>>(sty, affw, affb);
    wsq_kernel<<<(OC_ * IC_ + 255) / 256, 256>>>(cw);
    demod_kernel<<<B_, OC_>>>();
    {
        dim3 g(B_ * 8, 16);
        scale_xt_kernel<<<g, 256>>>(x);
    }
    repack_w_kernel<<<(9 * OC_ * IC_) / 256, 256>>>(cw);

    cudaFuncSetAttribute(conv_mma, cudaFuncAttributeMaxDynamicSharedMemorySize, SMEM_BYTES);
    dim3 grid(4, 128);
    conv_mma<<<grid, 128, SMEM_BYTES>>>(out);
}

// round 7
// speedup vs baseline: 7.2836x; 1.0281x over previous
#include <cuda_runtime.h>
#include <cuda_fp16.h>
#include <cstdint>
#include <math.h>

// ---------------------------------------------------------------- constants
#define B_     16
#define IC_    512
#define OC_    512
#define HW_    32
#define STYLE_ 512
#define AFF_SCALE 0.04419417382415922f   // 1/sqrt(512)
#define W_SCALE   0.014731391274719739f  // 1/sqrt(512*9)

// ---------------------------------------------------------------- scratch
__device__ float g_s   [B_ * IC_];
__device__ float g_s2  [B_ * IC_];
__device__ float g_cw2t[IC_ * OC_];
__device__ float g_d   [B_ * OC_];
// x planes: [dw 3][b 16][chunk 8][1120 rows][64 ic] halves, SW128-swizzled rows.
// rows 0..47 and 1072..1119 are zero padding (never written -> stay zero).
#define XPLANE_ROWS 1120
#define XPAD 48
__device__ __half g_x2 [3 * B_ * 8 * XPLANE_ROWS * 64];
// weights: [(tap*8+chunk)*4+ocb] tiles of [128 row][64 ic] halves, swizzled.
__device__ __half g_wk2[9 * 8 * 4 * 128 * 64];

// ---------------------------------------------------------------- utils
__device__ __forceinline__ uint32_t smem_u32(const void* p) {
    uint32_t a;
    asm("{ .reg .u64 t; cvta.to.shared.u64 t, %1; cvt.u32.u64 %0, t; }" : "=r"(a) : "l"(p));
    return a;
}
#define LDSM_X4(r0, r1, r2, r3, addr) \
    asm volatile("ldmatrix.sync.aligned.m8n8.x4.shared.b16 {%0,%1,%2,%3}, [%4];" \
                 : "=r"(r0), "=r"(r1), "=r"(r2), "=r"(r3) : "r"(addr))
#define MBAR_INIT(a, c) asm volatile("mbarrier.init.shared.b64 [%0], %1;" :: "r"(a), "r"(c) : "memory")
#define MBAR_EXPECT(a, tx) \
    asm volatile("mbarrier.arrive.expect_tx.shared.b64 _, [%0], %1;" :: "r"(a), "r"(tx) : "memory")
#define BULK_G2S(dst, src, sz, mbar) \
    asm volatile("cp.async.bulk.shared::cluster.global.mbarrier::complete_tx::bytes [%0], [%1], %2, [%3];" \
                 :: "r"(dst), "l"(src), "r"(sz), "r"(mbar) : "memory")
__device__ __forceinline__ void mbar_wait(uint32_t addr, uint32_t parity) {
    asm volatile(
        "{\n\t.reg .pred P;\n\t"
        "W_%=:\n\t"
        "mbarrier.try_wait.parity.shared.b64 P, [%0], %1;\n\t"
        "@P bra.uni D_%=;\n\t"
        "bra.uni W_%=;\n\t"
        "D_%=:\n\t}"
        :: "r"(addr), "r"(parity) : "memory");
}

// ---------------------------------------------------------------- prep kernels
__global__ void affine_kernel(const float* __restrict__ style,
                              const float* __restrict__ aff_w,
                              const float* __restrict__ aff_b) {
    int b = blockIdx.x, i = threadIdx.x;
    __shared__ float st[STYLE_];
    st[i] = style[b * STYLE_ + i];
    __syncthreads();
    const float* wrow = aff_w + (size_t)i * STYLE_;
    float acc = 0.f;
    #pragma unroll 8
    for (int j = 0; j < STYLE_; j++) acc = fmaf(wrow[j], st[j], acc);
    float sp = (acc * AFF_SCALE + aff_b[i] + 1.0f) * W_SCALE;
    g_s [b * IC_ + i] = sp;
    g_s2[b * IC_ + i] = sp * sp;
}

__global__ void wsq_kernel(const float* __restrict__ cw) {
    int idx = blockIdx.x * blockDim.x + threadIdx.x;
    if (idx >= OC_ * IC_) return;
    int o = idx / IC_, i = idx - o * IC_;
    const float* p = cw + (size_t)idx * 9;
    float a = 0.f;
    #pragma unroll
    for (int k = 0; k < 9; k++) a = fmaf(p[k], p[k], a);
    g_cw2t[i * OC_ + o] = a;
}

__global__ void demod_kernel() {
    int b = blockIdx.x, o = threadIdx.x;
    __shared__ float s2[IC_];
    s2[o] = g_s2[b * IC_ + o];
    __syncthreads();
    float a = 0.f;
    #pragma unroll 8
    for (int i = 0; i < IC_; i++) a = fmaf(s2[i], g_cw2t[i * OC_ + o], a);
    g_d[b * OC_ + o] = rsqrtf(a + 1e-8f);
}

// Build g_x2: 3 dw-shifted, style-scaled, half, transposed, swizzled planes.
// grid (B_*8, 8): bx -> (b, chunk), by -> hquad (128 pix rows). block 256.
__global__ void build_x2_kernel(const float* __restrict__ x) {
    __shared__ float t[64][133];
    const int b     = blockIdx.x >> 3;
    const int chunk = blockIdx.x & 7;
    const int ic0   = chunk * 64;
    const int hq    = blockIdx.y;         // pix base hq*128
    const int tid   = threadIdx.x;

    #pragma unroll
    for (int e = 0; e < 8; e++) {
        int idx = e * 256 + tid;
        int ic = idx >> 5, p4 = idx & 31;
        float4 v = *(const float4*)(x + ((size_t)(b * IC_ + ic0 + ic)) * 1024 + hq * 128 + p4 * 4);
        float s = g_s[b * IC_ + ic0 + ic];
        t[ic][p4 * 4 + 0] = v.x * s;
        t[ic][p4 * 4 + 1] = v.y * s;
        t[ic][p4 * 4 + 2] = v.z * s;
        t[ic][p4 * 4 + 3] = v.w * s;
    }
    __syncthreads();

    #pragma unroll
    for (int dw = -1; dw <= 1; dw++) {
        #pragma unroll
        for (int e = 0; e < 4; e++) {
            int idx = e * 256 + tid;
            int r = idx >> 3, c = idx & 7;     // r: local pix row, c: 16B chunk
            int pc = r & 31;
            bool ok = (unsigned)(pc + dw) < 32u;
            int rs = ok ? (r + dw) : r;        // safe index
            uint32_t u[4];
            #pragma unroll
            for (int jj = 0; jj < 4; jj++) {
                float f0 = ok ? t[8 * c + 2 * jj][rs]     : 0.f;
                float f1 = ok ? t[8 * c + 2 * jj + 1][rs] : 0.f;
                __half2 hv = __floats2half2_rn(f0, f1);
                u[jj] = *(uint32_t*)&hv;
            }
            size_t q = (size_t)XPAD + hq * 128 + r;
            size_t base = ((((size_t)(dw + 1) * B_ + b) * 8 + chunk) * XPLANE_ROWS + q) * 64;
            uint4* dst = (uint4*)(g_x2 + base + ((c ^ (r & 7)) * 8));
            *dst = make_uint4(u[0], u[1], u[2], u[3]);
        }
    }
}

// Build g_wk2: contiguous swizzled A tiles. grid 288 (= tile index), block 256.
__global__ void build_w2_kernel(const float* __restrict__ cw) {
    const int bx   = blockIdx.x;           // ((tap*8+chunk)*4+ocb)
    const int ocb  = bx & 3;
    const int chunk = (bx >> 2) & 7;
    const int tap  = bx >> 5;
    const int tid  = threadIdx.x;
    #pragma unroll
    for (int e = 0; e < 4; e++) {
        int idx = e * 256 + tid;
        int row = idx >> 3, c = idx & 7;
        int o = ocb * 128 + row;
        uint32_t u[4];
        #pragma unroll
        for (int jj = 0; jj < 4; jj++) {
            float f0 = cw[((size_t)o * IC_ + chunk * 64 + 8 * c + 2 * jj) * 9 + tap];
            float f1 = cw[((size_t)o * IC_ + chunk * 64 + 8 * c + 2 * jj + 1) * 9 + tap];
            __half2 hv = __floats2half2_rn(f0, f1);
            u[jj] = *(uint32_t*)&hv;
        }
        uint4* dst = (uint4*)(g_wk2 + (size_t)bx * 8192 + row * 64 + ((c ^ (row & 7)) * 8));
        *dst = make_uint4(u[0], u[1], u[2], u[3]);
    }
}

// ---------------------------------------------------------------- fp16 mma conv
// GEMM M=512 x N=16384 x K=4608, K-chunk 64 -> 72 iters (chunk = it/9, tap = it%9).
// Stage = A tile 16KB + B tile 16KB, each one cp.async.bulk; 3-stage ring + mbarrier.
#define TILE_B 16384
#define STG_B  (2 * TILE_B)
#define NST    3
#define MB_OFF (NST * STG_B)
#define SMEM_CONV (MB_OFF + 64)
#define NITER 72

__global__ __launch_bounds__(128, 2)
void conv_mma(float* __restrict__ out) {
    extern __shared__ char smc[];
    const uint32_t sb = smem_u32(smc);
    const int tid = threadIdx.x;
    const int wid = tid >> 5, lane = tid & 31;
    const int g = lane >> 2, tg = lane & 3;
    const int m_w = (wid >> 1) * 64;
    const int n_w = (wid & 1) * 64;

    const int ocb = blockIdx.x;
    const int ocbase = ocb * 128;
    const int b  = blockIdx.y >> 3;
    const int h0 = (blockIdx.y & 7) * 4;

    // ldmatrix lane roles
    const int r7   = lane & 7;
    const int aRow = m_w + ((lane >> 3) & 1) * 8 + r7;
    const int aHi  = lane >> 4;                  // k +8 halves selector
    const int bRow = n_w + ((lane >> 4) ? 8 : 0) + r7;
    const int bHi  = (lane >> 3) & 1;

    if (tid == 0) {
        MBAR_INIT(sb + MB_OFF + 0, 1);
        MBAR_INIT(sb + MB_OFF + 8, 1);
        MBAR_INIT(sb + MB_OFF + 16, 1);
    }
    __syncthreads();

    float acc[4][8][4];
    #pragma unroll
    for (int mi = 0; mi < 4; mi++)
        #pragma unroll
        for (int ni = 0; ni < 8; ni++)
            #pragma unroll
            for (int c = 0; c < 4; c++) acc[mi][ni][c] = 0.f;

    // issue helper (tid 0 only): stage tile pair for iteration it into slot s
    auto issue = [&](int it, int s) {
        const int tap = it % 9, chunk = it / 9;
        const int dh = tap / 3 - 1, dw = tap % 3 - 1;
        const uint32_t mb = sb + MB_OFF + s * 8;
        MBAR_EXPECT(mb, (uint32_t)STG_B);
        const __half* asrc = g_wk2 + (size_t)((tap * 8 + chunk) * 4 + ocb) * 8192;
        BULK_G2S(sb + s * STG_B, asrc, TILE_B, mb);
        const size_t q0 = (size_t)XPAD + (h0 + dh) * 32;
        const __half* bsrc = g_x2 +
            ((((size_t)(dw + 1) * B_ + b) * 8 + chunk) * XPLANE_ROWS + q0) * 64;
        BULK_G2S(sb + s * STG_B + TILE_B, bsrc, TILE_B, mb);
    };

    if (tid == 0) { issue(0, 0); issue(1, 1); }

    uint32_t pha = 0, phb = 0, phc = 0;  // per-stage parity
    int slot = 0;

    #pragma unroll 1
    for (int it = 0; it < NITER; it++) {
        __syncthreads();                       // all reads of slot (it+2)%3 done
        if (tid == 0 && it + 2 < NITER) {
            int s2 = slot + 2; if (s2 >= 3) s2 -= 3;
            issue(it + 2, s2);
        }
        const uint32_t mb = sb + MB_OFF + slot * 8;
        uint32_t ph = (slot == 0) ? pha : (slot == 1 ? phb : phc);
        mbar_wait(mb, ph);
        if (slot == 0) pha ^= 1; else if (slot == 1) phb ^= 1; else phc ^= 1;

        const uint32_t Ab = sb + slot * STG_B;
        const uint32_t Bb = Ab + TILE_B;

        #pragma unroll
        for (int ks = 0; ks < 4; ks++) {
            uint32_t af[4][4], bf[4][4];
            const int cA = (2 * ks + aHi) ^ r7;
            const int cB = (2 * ks + bHi) ^ r7;
            #pragma unroll
            for (int mi = 0; mi < 4; mi++) {
                uint32_t addr = Ab + (uint32_t)(aRow + mi * 16) * 128 + cA * 16;
                LDSM_X4(af[mi][0], af[mi][1], af[mi][2], af[mi][3], addr);
            }
            #pragma unroll
            for (int nj = 0; nj < 4; nj++) {
                uint32_t addr = Bb + (uint32_t)(bRow + nj * 16) * 128 + cB * 16;
                LDSM_X4(bf[nj][0], bf[nj][1], bf[nj][2], bf[nj][3], addr);
            }
            #pragma unroll
            for (int mi = 0; mi < 4; mi++)
                #pragma unroll
                for (int ni = 0; ni < 8; ni++) {
                    const uint32_t b0 = bf[ni >> 1][(ni & 1) * 2];
                    const uint32_t b1 = bf[ni >> 1][(ni & 1) * 2 + 1];
                    asm volatile(
                        "mma.sync.aligned.m16n8k16.row.col.f32.f16.f16.f32 "
                        "{%0,%1,%2,%3}, {%4,%5,%6,%7}, {%8,%9}, {%0,%1,%2,%3};"
                        : "+f"(acc[mi][ni][0]), "+f"(acc[mi][ni][1]),
                          "+f"(acc[mi][ni][2]), "+f"(acc[mi][ni][3])
                        : "r"(af[mi][0]), "r"(af[mi][1]), "r"(af[mi][2]), "r"(af[mi][3]),
                          "r"(b0), "r"(b1));
                }
        }
        slot++; if (slot == 3) slot = 0;
    }

    // ---- epilogue: demodulate + store
    #pragma unroll
    for (int mi = 0; mi < 4; mi++) {
        const int r0 = m_w + mi * 16 + g;
        const float d0 = g_d[b * OC_ + ocbase + r0];
        const float d1 = g_d[b * OC_ + ocbase + r0 + 8];
        #pragma unroll
        for (int ni = 0; ni < 8; ni++) {
            const int col = n_w + ni * 8 + 2 * tg;
            const int h = h0 + (col >> 5), w = col & 31;
            float2* p0 = (float2*)(out + (((size_t)(b * OC_ + ocbase + r0)) * 32 + h) * 32 + w);
            float2* p1 = (float2*)(out + (((size_t)(b * OC_ + ocbase + r0 + 8)) * 32 + h) * 32 + w);
            float2 v0 = { acc[mi][ni][0] * d0, acc[mi][ni][1] * d0 };
            float2 v1 = { acc[mi][ni][2] * d1, acc[mi][ni][3] * d1 };
            *p0 = v0;
            *p1 = v1;
        }
    }
}

// ---------------------------------------------------------------- launch
extern "C" void kernel_launch(void* const* d_in, const int* in_sizes, int n_in,
                              void* d_out, int out_size) {
    const float* x    = (const float*)d_in[0];
    const float* sty  = (const float*)d_in[1];
    const float* affw = (const float*)d_in[2];
    const float* affb = (const float*)d_in[3];
    const float* cw   = (const float*)d_in[4];
    float* out = (float*)d_out;

    affine_kernel<<<B_, STYLE_>>>(sty, affw, affb);
    wsq_kernel<<<(OC_ * IC_ + 255) / 256, 256>>>(cw);
    demod_kernel<<<B_, OC_>>>();
    {
        dim3 g(B_ * 8, 8);
        build_x2_kernel<<<g, 256>>>(x);
    }
    build_w2_kernel<<<288, 256>>>(cw);

    cudaFuncSetAttribute(conv_mma, cudaFuncAttributeMaxDynamicSharedMemorySize, SMEM_CONV);
    dim3 grid(4, 128);
    conv_mma<<<grid, 128, SMEM_CONV>>>(out);
}

// round 8
// speedup vs baseline: 7.4680x; 1.0253x over previous
#include <cuda_runtime.h>
#include <cuda_fp16.h>
#include <cstdint>
#include <math.h>

// ---------------------------------------------------------------- constants
#define B_     16
#define IC_    512
#define OC_    512
#define HW_    32
#define STYLE_ 512
#define AFF_SCALE 0.04419417382415922f   // 1/sqrt(512)
#define W_SCALE   0.014731391274719739f  // 1/sqrt(512*9)

// ---------------------------------------------------------------- scratch
__device__ float g_s   [B_ * IC_];
__device__ float g_s2  [B_ * IC_];
__device__ float g_cw2t[IC_ * OC_];
__device__ float g_d   [B_ * OC_];
// x planes: [dw 3][b 16][chunk 8][1120 rows][64 ic] halves, swizzled rows.
// rows 0..47 and 1072..1119 are zero padding (never written -> stay zero).
#define XPLANE_ROWS 1120
#define XPAD 48
__device__ __half g_x2 [3 * B_ * 8 * XPLANE_ROWS * 64];
// weights: [(tap*8+chunk)*4+ocb] tiles of [128 row][64 ic] halves, swizzled.
__device__ __half g_wk2[9 * 8 * 4 * 128 * 64];

// ---------------------------------------------------------------- utils
__device__ __forceinline__ uint32_t smem_u32(const void* p) {
    uint32_t a;
    asm("{ .reg .u64 t; cvta.to.shared.u64 t, %1; cvt.u32.u64 %0, t; }" : "=r"(a) : "l"(p));
    return a;
}
#define LDSM_X4(r0, r1, r2, r3, addr) \
    asm volatile("ldmatrix.sync.aligned.m8n8.x4.shared.b16 {%0,%1,%2,%3}, [%4];" \
                 : "=r"(r0), "=r"(r1), "=r"(r2), "=r"(r3) : "r"(addr))
#define MBAR_INIT(a, c) asm volatile("mbarrier.init.shared.b64 [%0], %1;" :: "r"(a), "r"(c) : "memory")
#define MBAR_EXPECT(a, tx) \
    asm volatile("mbarrier.arrive.expect_tx.shared.b64 _, [%0], %1;" :: "r"(a), "r"(tx) : "memory")
#define BULK_G2S(dst, src, sz, mbar) \
    asm volatile("cp.async.bulk.shared::cluster.global.mbarrier::complete_tx::bytes [%0], [%1], %2, [%3];" \
                 :: "r"(dst), "l"(src), "r"(sz), "r"(mbar) : "memory")
__device__ __forceinline__ void mbar_wait(uint32_t addr, uint32_t parity) {
    asm volatile(
        "{\n\t.reg .pred P;\n\t"
        "W_%=:\n\t"
        "mbarrier.try_wait.parity.shared.b64 P, [%0], %1;\n\t"
        "@P bra.uni D_%=;\n\t"
        "bra.uni W_%=;\n\t"
        "D_%=:\n\t}"
        :: "r"(addr), "r"(parity) : "memory");
}

// ---------------------------------------------------------------- prep kernels
__global__ void affine_kernel(const float* __restrict__ style,
                              const float* __restrict__ aff_w,
                              const float* __restrict__ aff_b) {
    int b = blockIdx.x, i = threadIdx.x;
    __shared__ float st[STYLE_];
    st[i] = style[b * STYLE_ + i];
    __syncthreads();
    const float* wrow = aff_w + (size_t)i * STYLE_;
    float acc = 0.f;
    #pragma unroll 8
    for (int j = 0; j < STYLE_; j++) acc = fmaf(wrow[j], st[j], acc);
    float sp = (acc * AFF_SCALE + aff_b[i] + 1.0f) * W_SCALE;
    g_s [b * IC_ + i] = sp;
    g_s2[b * IC_ + i] = sp * sp;
}

__global__ void wsq_kernel(const float* __restrict__ cw) {
    int idx = blockIdx.x * blockDim.x + threadIdx.x;
    if (idx >= OC_ * IC_) return;
    int o = idx / IC_, i = idx - o * IC_;
    const float* p = cw + (size_t)idx * 9;
    float a = 0.f;
    #pragma unroll
    for (int k = 0; k < 9; k++) a = fmaf(p[k], p[k], a);
    g_cw2t[i * OC_ + o] = a;
}

__global__ void demod_kernel() {
    int b = blockIdx.x, o = threadIdx.x;
    __shared__ float s2[IC_];
    s2[o] = g_s2[b * IC_ + o];
    __syncthreads();
    float a = 0.f;
    #pragma unroll 8
    for (int i = 0; i < IC_; i++) a = fmaf(s2[i], g_cw2t[i * OC_ + o], a);
    g_d[b * OC_ + o] = rsqrtf(a + 1e-8f);
}

__global__ void zero_out_kernel(float4* __restrict__ out4) {
    out4[blockIdx.x * 256 + threadIdx.x] = make_float4(0.f, 0.f, 0.f, 0.f);
}

// Build g_x2: 3 dw-shifted, style-scaled, half, transposed, swizzled planes.
__global__ void build_x2_kernel(const float* __restrict__ x) {
    __shared__ float t[64][133];
    const int b     = blockIdx.x >> 3;
    const int chunk = blockIdx.x & 7;
    const int ic0   = chunk * 64;
    const int hq    = blockIdx.y;
    const int tid   = threadIdx.x;

    #pragma unroll
    for (int e = 0; e < 8; e++) {
        int idx = e * 256 + tid;
        int ic = idx >> 5, p4 = idx & 31;
        float4 v = *(const float4*)(x + ((size_t)(b * IC_ + ic0 + ic)) * 1024 + hq * 128 + p4 * 4);
        float s = g_s[b * IC_ + ic0 + ic];
        t[ic][p4 * 4 + 0] = v.x * s;
        t[ic][p4 * 4 + 1] = v.y * s;
        t[ic][p4 * 4 + 2] = v.z * s;
        t[ic][p4 * 4 + 3] = v.w * s;
    }
    __syncthreads();

    #pragma unroll
    for (int dw = -1; dw <= 1; dw++) {
        #pragma unroll
        for (int e = 0; e < 4; e++) {
            int idx = e * 256 + tid;
            int r = idx >> 3, c = idx & 7;
            int pc = r & 31;
            bool ok = (unsigned)(pc + dw) < 32u;
            int rs = ok ? (r + dw) : r;
            uint32_t u[4];
            #pragma unroll
            for (int jj = 0; jj < 4; jj++) {
                float f0 = ok ? t[8 * c + 2 * jj][rs]     : 0.f;
                float f1 = ok ? t[8 * c + 2 * jj + 1][rs] : 0.f;
                __half2 hv = __floats2half2_rn(f0, f1);
                u[jj] = *(uint32_t*)&hv;
            }
            size_t q = (size_t)XPAD + hq * 128 + r;
            size_t base = ((((size_t)(dw + 1) * B_ + b) * 8 + chunk) * XPLANE_ROWS + q) * 64;
            uint4* dst = (uint4*)(g_x2 + base + ((c ^ (r & 7)) * 8));
            *dst = make_uint4(u[0], u[1], u[2], u[3]);
        }
    }
}

__global__ void build_w2_kernel(const float* __restrict__ cw) {
    const int bx   = blockIdx.x;           // ((tap*8+chunk)*4+ocb)
    const int ocb  = bx & 3;
    const int chunk = (bx >> 2) & 7;
    const int tap  = bx >> 5;
    const int tid  = threadIdx.x;
    #pragma unroll
    for (int e = 0; e < 4; e++) {
        int idx = e * 256 + tid;
        int row = idx >> 3, c = idx & 7;
        int o = ocb * 128 + row;
        uint32_t u[4];
        #pragma unroll
        for (int jj = 0; jj < 4; jj++) {
            float f0 = cw[((size_t)o * IC_ + chunk * 64 + 8 * c + 2 * jj) * 9 + tap];
            float f1 = cw[((size_t)o * IC_ + chunk * 64 + 8 * c + 2 * jj + 1) * 9 + tap];
            __half2 hv = __floats2half2_rn(f0, f1);
            u[jj] = *(uint32_t*)&hv;
        }
        uint4* dst = (uint4*)(g_wk2 + (size_t)bx * 8192 + row * 64 + ((c ^ (row & 7)) * 8));
        *dst = make_uint4(u[0], u[1], u[2], u[3]);
    }
}

// ---------------------------------------------------------------- stream-K fp16 mma conv
// 512 tiles (4 ocb x 16 b x 8 hq) x 72 k-iters = 36864 units over 296 persistent CTAs.
// Each tile has <= 2 contributors -> fp32 atomicAdd of demodulated partials (deterministic:
// <= 2 commutative adds onto zeroed output).
#define TILE_B 16384
#define STG_B  (2 * TILE_B)
#define MB_OFF (3 * STG_B)
#define SMEM_CONV (MB_OFF + 64)
#define NTILES 512
#define KITERS 72
#define TOTUNITS (NTILES * KITERS)   // 36864
#define NCTA 296

__global__ __launch_bounds__(128, 2)
void conv_mma(float* __restrict__ out) {
    extern __shared__ char smc[];
    const uint32_t sb = smem_u32(smc);
    const int tid = threadIdx.x;
    const int wid = tid >> 5, lane = tid & 31;
    const int g = lane >> 2, tg = lane & 3;
    const int m_w = (wid >> 1) * 64;
    const int n_w = (wid & 1) * 64;

    const int r7   = lane & 7;
    const int aRow = m_w + ((lane >> 3) & 1) * 8 + r7;
    const int aHi  = lane >> 4;
    const int bRow = n_w + ((lane >> 4) ? 8 : 0) + r7;
    const int bHi  = (lane >> 3) & 1;

    const int bid = blockIdx.x;
    const int u0 = (int)(((long long)bid * TOTUNITS) / NCTA);
    const int u1 = (int)(((long long)(bid + 1) * TOTUNITS) / NCTA);

    if (tid == 0) {
        MBAR_INIT(sb + MB_OFF + 0, 1);
        MBAR_INIT(sb + MB_OFF + 8, 1);
        MBAR_INIT(sb + MB_OFF + 16, 1);
    }
    __syncthreads();

    float acc[4][8][4];
    #pragma unroll
    for (int mi = 0; mi < 4; mi++)
        #pragma unroll
        for (int ni = 0; ni < 8; ni++)
            #pragma unroll
            for (int c = 0; c < 4; c++) acc[mi][ni][c] = 0.f;

    // issue unit u into ring slot s (tid 0 only)
    auto issue = [&](int u, int s) {
        const int tile = u / KITERS;
        const int kit  = u - tile * KITERS;
        const int tap = kit % 9, chunk = kit / 9;
        const int dh = tap / 3 - 1, dw = tap % 3 - 1;
        const int ocb = tile >> 7;
        const int by  = tile & 127;
        const int bb  = by >> 3;
        const int h0  = (by & 7) * 4;
        const uint32_t mb = sb + MB_OFF + s * 8;
        MBAR_EXPECT(mb, (uint32_t)STG_B);
        const __half* asrc = g_wk2 + (size_t)((tap * 8 + chunk) * 4 + ocb) * 8192;
        BULK_G2S(sb + s * STG_B, asrc, TILE_B, mb);
        const size_t q0 = (size_t)XPAD + (h0 + dh) * 32;
        const __half* bsrc = g_x2 +
            ((((size_t)(dw + 1) * B_ + bb) * 8 + chunk) * XPLANE_ROWS + q0) * 64;
        BULK_G2S(sb + s * STG_B + TILE_B, bsrc, TILE_B, mb);
    };

    // flush demodulated partial of tile via atomics, zero acc
    auto flush = [&](int tile) {
        const int ocbase = (tile >> 7) * 128;
        const int by = tile & 127;
        const int bb = by >> 3;
        const int h0 = (by & 7) * 4;
        #pragma unroll
        for (int mi = 0; mi < 4; mi++) {
            const int r0 = m_w + mi * 16 + g;
            const float d0 = g_d[bb * OC_ + ocbase + r0];
            const float d1 = g_d[bb * OC_ + ocbase + r0 + 8];
            #pragma unroll
            for (int ni = 0; ni < 8; ni++) {
                const int col = n_w + ni * 8 + 2 * tg;
                const int h = h0 + (col >> 5), w = col & 31;
                float* p0 = out + (((size_t)(bb * OC_ + ocbase + r0)) * 32 + h) * 32 + w;
                float* p1 = out + (((size_t)(bb * OC_ + ocbase + r0 + 8)) * 32 + h) * 32 + w;
                atomicAdd(p0,     acc[mi][ni][0] * d0);
                atomicAdd(p0 + 1, acc[mi][ni][1] * d0);
                atomicAdd(p1,     acc[mi][ni][2] * d1);
                atomicAdd(p1 + 1, acc[mi][ni][3] * d1);
                acc[mi][ni][0] = acc[mi][ni][1] = acc[mi][ni][2] = acc[mi][ni][3] = 0.f;
            }
        }
    };

    if (tid == 0) {
        issue(u0, 0);
        if (u0 + 1 < u1) issue(u0 + 1, 1);
    }

    uint32_t pha = 0, phb = 0, phc = 0;
    int slot = 0;
    int cur_tile = u0 / KITERS;

    #pragma unroll 1
    for (int u = u0; u < u1; u++) {
        __syncthreads();                       // all warps done reading slot (slot+2)%3
        if (tid == 0 && u + 2 < u1) {
            int s2 = slot + 2; if (s2 >= 3) s2 -= 3;
            issue(u + 2, s2);
        }
        const int tile = u / KITERS;
        if (tile != cur_tile) { flush(cur_tile); cur_tile = tile; }

        const uint32_t mb = sb + MB_OFF + slot * 8;
        uint32_t ph = (slot == 0) ? pha : (slot == 1 ? phb : phc);
        mbar_wait(mb, ph);
        if (slot == 0) pha ^= 1; else if (slot == 1) phb ^= 1; else phc ^= 1;

        const uint32_t Ab = sb + slot * STG_B;
        const uint32_t Bb = Ab + TILE_B;

        #pragma unroll
        for (int ks = 0; ks < 4; ks++) {
            uint32_t af[4][4], bf[4][4];
            const int cA = (2 * ks + aHi) ^ r7;
            const int cB = (2 * ks + bHi) ^ r7;
            #pragma unroll
            for (int mi = 0; mi < 4; mi++) {
                uint32_t addr = Ab + (uint32_t)(aRow + mi * 16) * 128 + cA * 16;
                LDSM_X4(af[mi][0], af[mi][1], af[mi][2], af[mi][3], addr);
            }
            #pragma unroll
            for (int nj = 0; nj < 4; nj++) {
                uint32_t addr = Bb + (uint32_t)(bRow + nj * 16) * 128 + cB * 16;
                LDSM_X4(bf[nj][0], bf[nj][1], bf[nj][2], bf[nj][3], addr);
            }
            #pragma unroll
            for (int mi = 0; mi < 4; mi++)
                #pragma unroll
                for (int ni = 0; ni < 8; ni++) {
                    const uint32_t b0 = bf[ni >> 1][(ni & 1) * 2];
                    const uint32_t b1 = bf[ni >> 1][(ni & 1) * 2 + 1];
                    asm volatile(
                        "mma.sync.aligned.m16n8k16.row.col.f32.f16.f16.f32 "
                        "{%0,%1,%2,%3}, {%4,%5,%6,%7}, {%8,%9}, {%0,%1,%2,%3};"
                        : "+f"(acc[mi][ni][0]), "+f"(acc[mi][ni][1]),
                          "+f"(acc[mi][ni][2]), "+f"(acc[mi][ni][3])
                        : "r"(af[mi][0]), "r"(af[mi][1]), "r"(af[mi][2]), "r"(af[mi][3]),
                          "r"(b0), "r"(b1));
                }
        }
        slot++; if (slot == 3) slot = 0;
    }

    flush(cur_tile);
}

// ---------------------------------------------------------------- launch
extern "C" void kernel_launch(void* const* d_in, const int* in_sizes, int n_in,
                              void* d_out, int out_size) {
    const float* x    = (const float*)d_in[0];
    const float* sty  = (const float*)d_in[1];
    const float* affw = (const float*)d_in[2];
    const float* affb = (const float*)d_in[3];
    const float* cw   = (const float*)d_in[4];
    float* out = (float*)d_out;

    affine_kernel<<<B_, STYLE_>>>(sty, affw, affb);
    wsq_kernel<<<(OC_ * IC_ + 255) / 256, 256>>>(cw);
    demod_kernel<<<B_, OC_>>>();
    zero_out_kernel<<<(B_ * OC_ * HW_ * HW_) / 1024, 256>>>((float4*)out);
    {
        dim3 g(B_ * 8, 8);
        build_x2_kernel<<<g, 256>>>(x);
    }
    build_w2_kernel<<<288, 256>>>(cw);

    cudaFuncSetAttribute(conv_mma, cudaFuncAttributeMaxDynamicSharedMemorySize, SMEM_CONV);
    conv_mma<<<NCTA, 128, SMEM_CONV>>>(out);
}

// round 10
// speedup vs baseline: 7.5675x; 1.0133x over previous
#include <cuda_runtime.h>
#include <cuda_fp16.h>
#include <cstdint>
#include <math.h>

// ---------------------------------------------------------------- constants
#define B_     16
#define IC_    512
#define OC_    512
#define HW_    32
#define STYLE_ 512
#define AFF_SCALE 0.04419417382415922f   // 1/sqrt(512)
#define W_SCALE   0.014731391274719739f  // 1/sqrt(512*9)

// ---------------------------------------------------------------- scratch
__device__ float g_s   [B_ * IC_];
__device__ float g_s2  [B_ * IC_];
__device__ float g_cw2t[IC_ * OC_];
__device__ float g_d   [B_ * OC_];
// single x plane: [b 16][chunk 8][1120 rows][64 ic] halves, swizzled rows.
// rows 0..47 and 1072..1119 are zero padding (never written -> stay zero).
#define XPLANE_ROWS 1120
#define XPAD 48
__device__ __half g_x2 [B_ * 8 * XPLANE_ROWS * 64];
// weights: [(tap*8+chunk)*4+ocb] tiles of [128 row][64 ic] halves, swizzled.
__device__ __half g_wk2[9 * 8 * 4 * 128 * 64];

// ---------------------------------------------------------------- utils
__device__ __forceinline__ uint32_t smem_u32(const void* p) {
    uint32_t a;
    asm("{ .reg .u64 t; cvta.to.shared.u64 t, %1; cvt.u32.u64 %0, t; }" : "=r"(a) : "l"(p));
    return a;
}
#define LDSM_X4(r0, r1, r2, r3, addr) \
    asm volatile("ldmatrix.sync.aligned.m8n8.x4.shared.b16 {%0,%1,%2,%3}, [%4];" \
                 : "=r"(r0), "=r"(r1), "=r"(r2), "=r"(r3) : "r"(addr))
#define MBAR_INIT(a, c) asm volatile("mbarrier.init.shared.b64 [%0], %1;" :: "r"(a), "r"(c) : "memory")
#define MBAR_EXPECT(a, tx) \
    asm volatile("mbarrier.arrive.expect_tx.shared.b64 _, [%0], %1;" :: "r"(a), "r"(tx) : "memory")
#define BULK_G2S(dst, src, sz, mbar) \
    asm volatile("cp.async.bulk.shared::cluster.global.mbarrier::complete_tx::bytes [%0], [%1], %2, [%3];" \
                 :: "r"(dst), "l"(src), "r"(sz), "r"(mbar) : "memory")
__device__ __forceinline__ void mbar_wait(uint32_t addr, uint32_t parity) {
    asm volatile(
        "{\n\t.reg .pred P;\n\t"
        "W_%=:\n\t"
        "mbarrier.try_wait.parity.shared.b64 P, [%0], %1;\n\t"
        "@P bra.uni D_%=;\n\t"
        "bra.uni W_%=;\n\t"
        "D_%=:\n\t}"
        :: "r"(addr), "r"(parity) : "memory");
}

// ---------------------------------------------------------------- prep kernels
__global__ void affine_kernel(const float* __restrict__ style,
                              const float* __restrict__ aff_w,
                              const float* __restrict__ aff_b) {
    int b = blockIdx.x, i = threadIdx.x;
    __shared__ float st[STYLE_];
    st[i] = style[b * STYLE_ + i];
    __syncthreads();
    const float* wrow = aff_w + (size_t)i * STYLE_;
    float acc = 0.f;
    #pragma unroll 8
    for (int j = 0; j < STYLE_; j++) acc = fmaf(wrow[j], st[j], acc);
    float sp = (acc * AFF_SCALE + aff_b[i] + 1.0f) * W_SCALE;
    g_s [b * IC_ + i] = sp;
    g_s2[b * IC_ + i] = sp * sp;
}

__global__ void wsq_kernel(const float* __restrict__ cw) {
    int idx = blockIdx.x * blockDim.x + threadIdx.x;
    if (idx >= OC_ * IC_) return;
    int o = idx / IC_, i = idx - o * IC_;
    const float* p = cw + (size_t)idx * 9;
    float a = 0.f;
    #pragma unroll
    for (int k = 0; k < 9; k++) a = fmaf(p[k], p[k], a);
    g_cw2t[i * OC_ + o] = a;
}

__global__ void demod_kernel() {
    int b = blockIdx.x, o = threadIdx.x;
    __shared__ float s2[IC_];
    s2[o] = g_s2[b * IC_ + o];
    __syncthreads();
    float a = 0.f;
    #pragma unroll 8
    for (int i = 0; i < IC_; i++) a = fmaf(s2[i], g_cw2t[i * OC_ + o], a);
    g_d[b * OC_ + o] = rsqrtf(a + 1e-8f);
}

__global__ void zero_out_kernel(float4* __restrict__ out4) {
    out4[blockIdx.x * 256 + threadIdx.x] = make_float4(0.f, 0.f, 0.f, 0.f);
}

// Build the single x plane: style-scaled, half, transposed, swizzled.
__global__ void build_x2_kernel(const float* __restrict__ x) {
    __shared__ float t[64][133];
    const int b     = blockIdx.x >> 3;
    const int chunk = blockIdx.x & 7;
    const int ic0   = chunk * 64;
    const int hq    = blockIdx.y;
    const int tid   = threadIdx.x;

    #pragma unroll
    for (int e = 0; e < 8; e++) {
        int idx = e * 256 + tid;
        int ic = idx >> 5, p4 = idx & 31;
        float4 v = *(const float4*)(x + ((size_t)(b * IC_ + ic0 + ic)) * 1024 + hq * 128 + p4 * 4);
        float s = g_s[b * IC_ + ic0 + ic];
        t[ic][p4 * 4 + 0] = v.x * s;
        t[ic][p4 * 4 + 1] = v.y * s;
        t[ic][p4 * 4 + 2] = v.z * s;
        t[ic][p4 * 4 + 3] = v.w * s;
    }
    __syncthreads();

    #pragma unroll
    for (int e = 0; e < 4; e++) {
        int idx = e * 256 + tid;
        int r = idx >> 3, c = idx & 7;
        uint32_t u[4];
        #pragma unroll
        for (int jj = 0; jj < 4; jj++) {
            __half2 hv = __floats2half2_rn(t[8 * c + 2 * jj][r], t[8 * c + 2 * jj + 1][r]);
            u[jj] = *(uint32_t*)&hv;
        }
        size_t q = (size_t)XPAD + hq * 128 + r;
        size_t base = (((size_t)b * 8 + chunk) * XPLANE_ROWS + q) * 64;
        // swizzle keyed to PLANE row q
        uint4* dst = (uint4*)(g_x2 + base + ((c ^ ((int)q & 7)) * 8));
        *dst = make_uint4(u[0], u[1], u[2], u[3]);
    }
}

__global__ void build_w2_kernel(const float* __restrict__ cw) {
    const int bx   = blockIdx.x;           // ((tap*8+chunk)*4+ocb)
    const int ocb  = bx & 3;
    const int chunk = (bx >> 2) & 7;
    const int tap  = bx >> 5;
    const int tid  = threadIdx.x;
    #pragma unroll
    for (int e = 0; e < 4; e++) {
        int idx = e * 256 + tid;
        int row = idx >> 3, c = idx & 7;
        int o = ocb * 128 + row;
        uint32_t u[4];
        #pragma unroll
        for (int jj = 0; jj < 4; jj++) {
            float f0 = cw[((size_t)o * IC_ + chunk * 64 + 8 * c + 2 * jj) * 9 + tap];
            float f1 = cw[((size_t)o * IC_ + chunk * 64 + 8 * c + 2 * jj + 1) * 9 + tap];
            __half2 hv = __floats2half2_rn(f0, f1);
            u[jj] = *(uint32_t*)&hv;
        }
        uint4* dst = (uint4*)(g_wk2 + (size_t)bx * 8192 + row * 64 + ((c ^ (row & 7)) * 8));
        *dst = make_uint4(u[0], u[1], u[2], u[3]);
    }
}

// ---------------------------------------------------------------- stream-K fp16 mma conv
// B tiles staged from the single plane with a dw row-shift. Because the plane's
// swizzle is keyed to the plane row p = smem_row + q0 and q0 = dw (mod 8), the
// B deswizzle XORs with ((r7 + dw) & 7). The 4 wrap-invalid rows per tile are
// zeroed in smem post-copy. <=2 contributors per tile -> deterministic atomicAdd.
#define TILE_B 16384
#define STG_B  (2 * TILE_B)
#define MB_OFF (3 * STG_B)
#define SMEM_CONV (MB_OFF + 64)
#define NTILES 512
#define KITERS 72
#define TOTUNITS (NTILES * KITERS)   // 36864
#define NCTA 296

__global__ __launch_bounds__(128, 2)
void conv_mma(float* __restrict__ out) {
    extern __shared__ char smc[];
    const uint32_t sb = smem_u32(smc);
    const int tid = threadIdx.x;
    const int wid = tid >> 5, lane = tid & 31;
    const int g = lane >> 2, tg = lane & 3;
    const int m_w = (wid >> 1) * 64;
    const int n_w = (wid & 1) * 64;

    const int r7   = lane & 7;
    const int aRow = m_w + ((lane >> 3) & 1) * 8 + r7;
    const int aHi  = lane >> 4;
    const int bRow = n_w + ((lane >> 4) ? 8 : 0) + r7;
    const int bHi  = (lane >> 3) & 1;

    const int bid = blockIdx.x;
    const int u0 = (int)(((long long)bid * TOTUNITS) / NCTA);
    const int u1 = (int)(((long long)(bid + 1) * TOTUNITS) / NCTA);

    if (tid == 0) {
        MBAR_INIT(sb + MB_OFF + 0, 1);
        MBAR_INIT(sb + MB_OFF + 8, 1);
        MBAR_INIT(sb + MB_OFF + 16, 1);
    }
    __syncthreads();

    float acc[4][8][4];
    #pragma unroll
    for (int mi = 0; mi < 4; mi++)
        #pragma unroll
        for (int ni = 0; ni < 8; ni++)
            #pragma unroll
            for (int c = 0; c < 4; c++) acc[mi][ni][c] = 0.f;

    auto issue = [&](int u, int s) {
        const int tile = u / KITERS;
        const int kit  = u - tile * KITERS;
        const int tap = kit % 9, chunk = kit / 9;
        const int dh = tap / 3 - 1, dw = tap % 3 - 1;
        const int ocb = tile >> 7;
        const int by  = tile & 127;
        const int bb  = by >> 3;
        const int h0  = (by & 7) * 4;
        const uint32_t mb = sb + MB_OFF + s * 8;
        MBAR_EXPECT(mb, (uint32_t)STG_B);
        const __half* asrc = g_wk2 + (size_t)((tap * 8 + chunk) * 4 + ocb) * 8192;
        BULK_G2S(sb + s * STG_B, asrc, TILE_B, mb);
        const int q0 = XPAD + (h0 + dh) * 32 + dw;   // dw = row shift in pix-major plane
        const __half* bsrc = g_x2 + (((size_t)bb * 8 + chunk) * XPLANE_ROWS + q0) * 64;
        BULK_G2S(sb + s * STG_B + TILE_B, bsrc, TILE_B, mb);
    };

    auto flush = [&](int tile) {
        const int ocbase = (tile >> 7) * 128;
        const int by = tile & 127;
        const int bb = by >> 3;
        const int h0 = (by & 7) * 4;
        #pragma unroll
        for (int mi = 0; mi < 4; mi++) {
            const int r0 = m_w + mi * 16 + g;
            const float d0 = g_d[bb * OC_ + ocbase + r0];
            const float d1 = g_d[bb * OC_ + ocbase + r0 + 8];
            #pragma unroll
            for (int ni = 0; ni < 8; ni++) {
                const int col = n_w + ni * 8 + 2 * tg;
                const int h = h0 + (col >> 5), w = col & 31;
                float* p0 = out + (((size_t)(bb * OC_ + ocbase + r0)) * 32 + h) * 32 + w;
                float* p1 = out + (((size_t)(bb * OC_ + ocbase + r0 + 8)) * 32 + h) * 32 + w;
                atomicAdd(p0,     acc[mi][ni][0] * d0);
                atomicAdd(p0 + 1, acc[mi][ni][1] * d0);
                atomicAdd(p1,     acc[mi][ni][2] * d1);
                atomicAdd(p1 + 1, acc[mi][ni][3] * d1);
                acc[mi][ni][0] = acc[mi][ni][1] = acc[mi][ni][2] = acc[mi][ni][3] = 0.f;
            }
        }
    };

    if (tid == 0) {
        issue(u0, 0);
        if (u0 + 1 < u1) issue(u0 + 1, 1);
    }

    uint32_t pha = 0, phb = 0, phc = 0;
    int slot = 0;
    int cur_tile = u0 / KITERS;

    #pragma unroll 1
    for (int u = u0; u < u1; u++) {
        __syncthreads();                       // all warps done reading slot (slot+2)%3
        if (tid == 0 && u + 2 < u1) {
            int s2 = slot + 2; if (s2 >= 3) s2 -= 3;
            issue(u + 2, s2);
        }
        const int tile = u / KITERS;
        if (tile != cur_tile) { flush(cur_tile); cur_tile = tile; }

        const uint32_t mb = sb + MB_OFF + slot * 8;
        uint32_t ph = (slot == 0) ? pha : (slot == 1 ? phb : phc);
        mbar_wait(mb, ph);
        if (slot == 0) pha ^= 1; else if (slot == 1) phb ^= 1; else phc ^= 1;

        const uint32_t Ab = sb + slot * STG_B;
        const uint32_t Bb = Ab + TILE_B;

        const int kit = u - tile * KITERS;
        const int tap = kit % 9;
        const int dwc = tap % 3 - 1;
        const int bX  = (r7 + dwc) & 7;        // B deswizzle key = plane row & 7

        // zero the 4 wrap-invalid rows of the B tile (dw != 0 only)
        if (dwc != 0 && tid < 32) {
            int row = ((tid >> 3) << 5) + (dwc > 0 ? 31 : 0);
            uint32_t addr = Bb + (uint32_t)row * 128 + (tid & 7) * 16;
            asm volatile("st.shared.v4.b32 [%0], {%1,%1,%1,%1};"
                         :: "r"(addr), "r"(0) : "memory");
        }
        __syncthreads();

        // register-stage double-buffered fragment pipeline
        uint32_t af[2][4][4], bf[2][4][4];
        {
            const int cA = aHi ^ r7, cB = bHi ^ bX;
            #pragma unroll
            for (int mi = 0; mi < 4; mi++)
                LDSM_X4(af[0][mi][0], af[0][mi][1], af[0][mi][2], af[0][mi][3],
                        Ab + (uint32_t)(aRow + mi * 16) * 128 + cA * 16);
            #pragma unroll
            for (int nj = 0; nj < 4; nj++)
                LDSM_X4(bf[0][nj][0], bf[0][nj][1], bf[0][nj][2], bf[0][nj][3],
                        Bb + (uint32_t)(bRow + nj * 16) * 128 + cB * 16);
        }
        #pragma unroll
        for (int ks = 0; ks < 4; ks++) {
            const int cb = ks & 1;
            if (ks < 3) {
                const int nb = cb ^ 1;
                const int cA = (2 * (ks + 1) + aHi) ^ r7;
                const int cB = (2 * (ks + 1) + bHi) ^ bX;
                #pragma unroll
                for (int mi = 0; mi < 4; mi++)
                    LDSM_X4(af[nb][mi][0], af[nb][mi][1], af[nb][mi][2], af[nb][mi][3],
                            Ab + (uint32_t)(aRow + mi * 16) * 128 + cA * 16);
                #pragma unroll
                for (int nj = 0; nj < 4; nj++)
                    LDSM_X4(bf[nb][nj][0], bf[nb][nj][1], bf[nb][nj][2], bf[nb][nj][3],
                            Bb + (uint32_t)(bRow + nj * 16) * 128 + cB * 16);
            }
            #pragma unroll
            for (int mi = 0; mi < 4; mi++)
                #pragma unroll
                for (int ni = 0; ni < 8; ni++) {
                    const uint32_t b0 = bf[cb][ni >> 1][(ni & 1) * 2];
                    const uint32_t b1 = bf[cb][ni >> 1][(ni & 1) * 2 + 1];
                    asm volatile(
                        "mma.sync.aligned.m16n8k16.row.col.f32.f16.f16.f32 "
                        "{%0,%1,%2,%3}, {%4,%5,%6,%7}, {%8,%9}, {%0,%1,%2,%3};"
                        : "+f"(acc[mi][ni][0]), "+f"(acc[mi][ni][1]),
                          "+f"(acc[mi][ni][2]), "+f"(acc[mi][ni][3])
                        : "r"(af[cb][mi][0]), "r"(af[cb][mi][1]),
                          "r"(af[cb][mi][2]), "r"(af[cb][mi][3]),
                          "r"(b0), "r"(b1));
                }
        }
        slot++; if (slot == 3) slot = 0;
    }

    flush(cur_tile);
}

// ---------------------------------------------------------------- launch
extern "C" void kernel_launch(void* const* d_in, const int* in_sizes, int n_in,
                              void* d_out, int out_size) {
    const float* x    = (const float*)d_in[0];
    const float* sty  = (const float*)d_in[1];
    const float* affw = (const float*)d_in[2];
    const float* affb = (const float*)d_in[3];
    const float* cw   = (const float*)d_in[4];
    float* out = (float*)d_out;

    affine_kernel<<<B_, STYLE_>>>(sty, affw, affb);
    wsq_kernel<<<(OC_ * IC_ + 255) / 256, 256>>>(cw);
    demod_kernel<<<B_, OC_>>>();
    zero_out_kernel<<<(B_ * OC_ * HW_ * HW_) / 1024, 256>>>((float4*)out);
    {
        dim3 g(B_ * 8, 8);
        build_x2_kernel<<<g, 256>>>(x);
    }
    build_w2_kernel<<<288, 256>>>(cw);

    cudaFuncSetAttribute(conv_mma, cudaFuncAttributeMaxDynamicSharedMemorySize, SMEM_CONV);
    conv_mma<<<NCTA, 128, SMEM_CONV>>>(out);
}

// round 12
// speedup vs baseline: 7.7063x; 1.0183x over previous
#include <cuda_runtime.h>
#include <cuda_fp16.h>
#include <cstdint>
#include <math.h>

// ---------------------------------------------------------------- constants
#define B_     16
#define IC_    512
#define OC_    512
#define HW_    32
#define STYLE_ 512
#define AFF_SCALE 0.04419417382415922f   // 1/sqrt(512)
#define W_SCALE   0.014731391274719739f  // 1/sqrt(512*9)

// ---------------------------------------------------------------- scratch
__device__ float g_s   [B_ * IC_];
__device__ float g_cw2t[IC_ * OC_];
__device__ float g_d   [B_ * OC_];
// padded x plane: [b 16][chunk 8][1156 rows][64 ic] halves, swizzled rows.
// row q = (h+1)*34 + (w+1), h,w in [-1,32]; pad rows/cols never written -> zero.
#define XROWS 1156
__device__ __half g_x2 [B_ * 8 * XROWS * 64];
// weights: [(tap*8+chunk)*4+ocb] tiles of [128 row][64 ic] halves, swizzled.
__device__ __half g_wk2[9 * 8 * 4 * 128 * 64];

// ---------------------------------------------------------------- utils
__device__ __forceinline__ uint32_t smem_u32(const void* p) {
    uint32_t a;
    asm("{ .reg .u64 t; cvta.to.shared.u64 t, %1; cvt.u32.u64 %0, t; }" : "=r"(a) : "l"(p));
    return a;
}
#define LDSM_X4(r0, r1, r2, r3, addr) \
    asm volatile("ldmatrix.sync.aligned.m8n8.x4.shared.b16 {%0,%1,%2,%3}, [%4];" \
                 : "=r"(r0), "=r"(r1), "=r"(r2), "=r"(r3) : "r"(addr))
#define MBAR_INIT(a, c) asm volatile("mbarrier.init.shared.b64 [%0], %1;" :: "r"(a), "r"(c) : "memory")
#define MBAR_EXPECT(a, tx) \
    asm volatile("mbarrier.arrive.expect_tx.shared.b64 _, [%0], %1;" :: "r"(a), "r"(tx) : "memory")
#define BULK_G2S(dst, src, sz, mbar) \
    asm volatile("cp.async.bulk.shared::cluster.global.mbarrier::complete_tx::bytes [%0], [%1], %2, [%3];" \
                 :: "r"(dst), "l"(src), "r"(sz), "r"(mbar) : "memory")
__device__ __forceinline__ void mbar_wait(uint32_t addr, uint32_t parity) {
    asm volatile(
        "{\n\t.reg .pred P;\n\t"
        "W_%=:\n\t"
        "mbarrier.try_wait.parity.shared.b64 P, [%0], %1;\n\t"
        "@P bra.uni D_%=;\n\t"
        "bra.uni W_%=;\n\t"
        "D_%=:\n\t}"
        :: "r"(addr), "r"(parity) : "memory");
}

// ---------------------------------------------------------------- prep kernels
// wsq + output zeroing fused. grid 1024 x 256.
__global__ void wsq_zero_kernel(const float* __restrict__ cw, float4* __restrict__ out4) {
    int idx = blockIdx.x * blockDim.x + threadIdx.x;
    if (idx < OC_ * IC_) {
        int o = idx / IC_, i = idx - o * IC_;
        const float* p = cw + (size_t)idx * 9;
        float a = 0.f;
        #pragma unroll
        for (int k = 0; k < 9; k++) a = fmaf(p[k], p[k], a);
        g_cw2t[i * OC_ + o] = a;
    }
    const float4 z = make_float4(0.f, 0.f, 0.f, 0.f);
    #pragma unroll
    for (int e = 0; e < 8; e++)
        out4[e * 262144 + idx] = z;
}

// affine + demod fused: block b, 512 threads.
__global__ void affine_demod_kernel(const float* __restrict__ style,
                                    const float* __restrict__ aff_w,
                                    const float* __restrict__ aff_b) {
    int b = blockIdx.x, i = threadIdx.x;
    __shared__ float st[STYLE_];
    __shared__ float s2[IC_];
    st[i] = style[b * STYLE_ + i];
    __syncthreads();
    const float* wrow = aff_w + (size_t)i * STYLE_;
    float acc = 0.f;
    #pragma unroll 8
    for (int j = 0; j < STYLE_; j++) acc = fmaf(wrow[j], st[j], acc);
    float sp = (acc * AFF_SCALE + aff_b[i] + 1.0f) * W_SCALE;
    g_s[b * IC_ + i] = sp;
    s2[i] = sp * sp;
    __syncthreads();
    float a = 0.f;
    #pragma unroll 8
    for (int k = 0; k < IC_; k++) a = fmaf(s2[k], g_cw2t[k * OC_ + i], a);
    g_d[b * OC_ + i] = rsqrtf(a + 1e-8f);
}

// Build the padded x plane: style-scaled, half, transposed, swizzled.
// grid (B_*8, 8): bx -> (b, chunk), by -> 128-pixel group. block 256.
__global__ void build_x2_kernel(const float* __restrict__ x) {
    __shared__ float t[64][133];
    const int b     = blockIdx.x >> 3;
    const int chunk = blockIdx.x & 7;
    const int ic0   = chunk * 64;
    const int hq    = blockIdx.y;
    const int tid   = threadIdx.x;

    #pragma unroll
    for (int e = 0; e < 8; e++) {
        int idx = e * 256 + tid;
        int ic = idx >> 5, p4 = idx & 31;
        float4 v = *(const float4*)(x + ((size_t)(b * IC_ + ic0 + ic)) * 1024 + hq * 128 + p4 * 4);
        float s = g_s[b * IC_ + ic0 + ic];
        t[ic][p4 * 4 + 0] = v.x * s;
        t[ic][p4 * 4 + 1] = v.y * s;
        t[ic][p4 * 4 + 2] = v.z * s;
        t[ic][p4 * 4 + 3] = v.w * s;
    }
    __syncthreads();

    #pragma unroll
    for (int e = 0; e < 4; e++) {
        int idx = e * 256 + tid;
        int r = idx >> 3, c = idx & 7;          // r = local pixel, c = 16B chunk
        uint32_t u[4];
        #pragma unroll
        for (int jj = 0; jj < 4; jj++) {
            __half2 hv = __floats2half2_rn(t[8 * c + 2 * jj][r], t[8 * c + 2 * jj + 1][r]);
            u[jj] = *(uint32_t*)&hv;
        }
        const int h = hq * 4 + (r >> 5), w = r & 31;
        const int q = (h + 1) * 34 + (w + 1);   // padded plane row
        size_t base = (((size_t)b * 8 + chunk) * XROWS + q) * 64;
        uint4* dst = (uint4*)(g_x2 + base + ((c ^ (q & 7)) * 8));
        *dst = make_uint4(u[0], u[1], u[2], u[3]);
    }
}

__global__ void build_w2_kernel(const float* __restrict__ cw) {
    const int bx   = blockIdx.x;           // ((tap*8+chunk)*4+ocb)
    const int ocb  = bx & 3;
    const int chunk = (bx >> 2) & 7;
    const int tap  = bx >> 5;
    const int tid  = threadIdx.x;
    #pragma unroll
    for (int e = 0; e < 4; e++) {
        int idx = e * 256 + tid;
        int row = idx >> 3, c = idx & 7;
        int o = ocb * 128 + row;
        uint32_t u[4];
        #pragma unroll
        for (int jj = 0; jj < 4; jj++) {
            float f0 = cw[((size_t)o * IC_ + chunk * 64 + 8 * c + 2 * jj) * 9 + tap];
            float f1 = cw[((size_t)o * IC_ + chunk * 64 + 8 * c + 2 * jj + 1) * 9 + tap];
            __half2 hv = __floats2half2_rn(f0, f1);
            u[jj] = *(uint32_t*)&hv;
        }
        uint4* dst = (uint4*)(g_wk2 + (size_t)bx * 8192 + row * 64 + ((c ^ (row & 7)) * 8));
        *dst = make_uint4(u[0], u[1], u[2], u[3]);
    }
}

// ---------------------------------------------------------------- stream-K fp16 mma conv
// B staged from the padded plane as 4 contiguous 4KB row-runs (halo zeros baked
// into the plane). Deswizzle key per lane: (base + 2*pr + r7) & 7, base from
// (h0+dh, dw). Single __syncthreads per iter. <=2 contributors per tile ->
// deterministic atomicAdd onto zeroed output.
#define TILE_B 16384
#define STG_B  (2 * TILE_B)
#define MB_OFF (3 * STG_B)
#define SMEM_CONV (MB_OFF + 64)
#define NTILES 512
#define KITERS 72
#define TOTUNITS (NTILES * KITERS)   // 36864
#define NCTA 296

__global__ __launch_bounds__(128, 2)
void conv_mma(float* __restrict__ out) {
    extern __shared__ char smc[];
    const uint32_t sb = smem_u32(smc);
    const int tid = threadIdx.x;
    const int wid = tid >> 5, lane = tid & 31;
    const int g = lane >> 2, tg = lane & 3;
    const int m_w = (wid >> 1) * 64;
    const int n_w = (wid & 1) * 64;

    const int r7   = lane & 7;
    const int aRow = m_w + ((lane >> 3) & 1) * 8 + r7;
    const int aHi  = lane >> 4;
    const int bRow = n_w + ((lane >> 4) ? 8 : 0) + r7;
    const int bHi  = (lane >> 3) & 1;

    const int bid = blockIdx.x;
    const int u0 = (int)(((long long)bid * TOTUNITS) / NCTA);
    const int u1 = (int)(((long long)(bid + 1) * TOTUNITS) / NCTA);

    if (tid == 0) {
        MBAR_INIT(sb + MB_OFF + 0, 1);
        MBAR_INIT(sb + MB_OFF + 8, 1);
        MBAR_INIT(sb + MB_OFF + 16, 1);
    }
    __syncthreads();

    float acc[4][8][4];
    #pragma unroll
    for (int mi = 0; mi < 4; mi++)
        #pragma unroll
        for (int ni = 0; ni < 8; ni++)
            #pragma unroll
            for (int c = 0; c < 4; c++) acc[mi][ni][c] = 0.f;

    auto issue = [&](int u, int s) {
        const int tile = u / KITERS;
        const int kit  = u - tile * KITERS;
        const int tap = kit % 9, chunk = kit / 9;
        const int dh = tap / 3 - 1, dw = tap % 3 - 1;
        const int ocb = tile >> 7;
        const int by  = tile & 127;
        const int bb  = by >> 3;
        const int h0  = (by & 7) * 4;
        const uint32_t mb = sb + MB_OFF + s * 8;
        MBAR_EXPECT(mb, (uint32_t)STG_B);
        const __half* asrc = g_wk2 + (size_t)((tap * 8 + chunk) * 4 + ocb) * 8192;
        BULK_G2S(sb + s * STG_B, asrc, TILE_B, mb);
        const __half* bplane = g_x2 + ((size_t)bb * 8 + chunk) * (XROWS * 64);
        #pragma unroll
        for (int pr = 0; pr < 4; pr++) {
            const int q = (h0 + dh + pr + 1) * 34 + (dw + 1);
            BULK_G2S(sb + s * STG_B + TILE_B + pr * 4096, bplane + (size_t)q * 64, 4096, mb);
        }
    };

    auto flush = [&](int tile) {
        const int ocbase = (tile >> 7) * 128;
        const int by = tile & 127;
        const int bb = by >> 3;
        const int h0 = (by & 7) * 4;
        #pragma unroll
        for (int mi = 0; mi < 4; mi++) {
            const int r0 = m_w + mi * 16 + g;
            const float d0 = g_d[bb * OC_ + ocbase + r0];
            const float d1 = g_d[bb * OC_ + ocbase + r0 + 8];
            #pragma unroll
            for (int ni = 0; ni < 8; ni++) {
                const int col = n_w + ni * 8 + 2 * tg;
                const int h = h0 + (col >> 5), w = col & 31;
                float* p0 = out + (((size_t)(bb * OC_ + ocbase + r0)) * 32 + h) * 32 + w;
                float* p1 = out + (((size_t)(bb * OC_ + ocbase + r0 + 8)) * 32 + h) * 32 + w;
                atomicAdd(p0,     acc[mi][ni][0] * d0);
                atomicAdd(p0 + 1, acc[mi][ni][1] * d0);
                atomicAdd(p1,     acc[mi][ni][2] * d1);
                atomicAdd(p1 + 1, acc[mi][ni][3] * d1);
                acc[mi][ni][0] = acc[mi][ni][1] = acc[mi][ni][2] = acc[mi][ni][3] = 0.f;
            }
        }
    };

    if (tid == 0) {
        issue(u0, 0);
        if (u0 + 1 < u1) issue(u0 + 1, 1);
    }

    uint32_t pha = 0, phb = 0, phc = 0;
    int slot = 0;
    int cur_tile = u0 / KITERS;

    #pragma unroll 1
    for (int u = u0; u < u1; u++) {
        __syncthreads();                       // all warps done reading the reused slot
        if (tid == 0 && u + 2 < u1) {
            int s2 = slot + 2; if (s2 >= 3) s2 -= 3;
            issue(u + 2, s2);
        }
        const int tile = u / KITERS;
        if (tile != cur_tile) { flush(cur_tile); cur_tile = tile; }

        const uint32_t mb = sb + MB_OFF + slot * 8;
        uint32_t ph = (slot == 0) ? pha : (slot == 1 ? phb : phc);
        mbar_wait(mb, ph);
        if (slot == 0) pha ^= 1; else if (slot == 1) phb ^= 1; else phc ^= 1;

        const uint32_t Ab = sb + slot * STG_B;
        const uint32_t Bb = Ab + TILE_B;

        // per-iter B deswizzle base: plane row q = (h0+dh+pr+1)*34 + dw+1+w
        const int kit = u - tile * KITERS;
        const int tap = kit % 9;
        const int dh  = tap / 3 - 1, dwc = tap % 3 - 1;
        const int h0  = ((tile & 127) & 7) * 4;
        const int kbase = (2 * (h0 + dh + 1) + dwc + 1) & 7;

        // precompute per-nj B addresses/keys (ks-invariant)
        uint32_t bAdr[4]; int bKey[4];
        #pragma unroll
        for (int nj = 0; nj < 4; nj++) {
            const int rowp = bRow + nj * 16;
            bAdr[nj] = Bb + (uint32_t)rowp * 128;
            bKey[nj] = (kbase + 2 * (rowp >> 5) + r7) & 7;
        }

        // register-stage double-buffered fragment pipeline
        uint32_t af[2][4][4], bf[2][4][4];
        {
            const int cA = aHi ^ r7;
            #pragma unroll
            for (int mi = 0; mi < 4; mi++)
                LDSM_X4(af[0][mi][0], af[0][mi][1], af[0][mi][2], af[0][mi][3],
                        Ab + (uint32_t)(aRow + mi * 16) * 128 + cA * 16);
            #pragma unroll
            for (int nj = 0; nj < 4; nj++)
                LDSM_X4(bf[0][nj][0], bf[0][nj][1], bf[0][nj][2], bf[0][nj][3],
                        bAdr[nj] + ((bHi ^ bKey[nj]) * 16));
        }
        #pragma unroll
        for (int ks = 0; ks < 4; ks++) {
            const int cb = ks & 1;
            if (ks < 3) {
                const int nb = cb ^ 1;
                const int cA = (2 * (ks + 1) + aHi) ^ r7;
                #pragma unroll
                for (int mi = 0; mi < 4; mi++)
                    LDSM_X4(af[nb][mi][0], af[nb][mi][1], af[nb][mi][2], af[nb][mi][3],
                            Ab + (uint32_t)(aRow + mi * 16) * 128 + cA * 16);
                #pragma unroll
                for (int nj = 0; nj < 4; nj++)
                    LDSM_X4(bf[nb][nj][0], bf[nb][nj][1], bf[nb][nj][2], bf[nb][nj][3],
                            bAdr[nj] + (((2 * (ks + 1) + bHi) ^ bKey[nj]) * 16));
            }
            #pragma unroll
            for (int mi = 0; mi < 4; mi++)
                #pragma unroll
                for (int ni = 0; ni < 8; ni++) {
                    const uint32_t b0 = bf[cb][ni >> 1][(ni & 1) * 2];
                    const uint32_t b1 = bf[cb][ni >> 1][(ni & 1) * 2 + 1];
                    asm volatile(
                        "mma.sync.aligned.m16n8k16.row.col.f32.f16.f16.f32 "
                        "{%0,%1,%2,%3}, {%4,%5,%6,%7}, {%8,%9}, {%0,%1,%2,%3};"
                        : "+f"(acc[mi][ni][0]), "+f"(acc[mi][ni][1]),
                          "+f"(acc[mi][ni][2]), "+f"(acc[mi][ni][3])
                        : "r"(af[cb][mi][0]), "r"(af[cb][mi][1]),
                          "r"(af[cb][mi][2]), "r"(af[cb][mi][3]),
                          "r"(b0), "r"(b1));
                }
        }
        slot++; if (slot == 3) slot = 0;
    }

    flush(cur_tile);
}

// ---------------------------------------------------------------- launch
extern "C" void kernel_launch(void* const* d_in, const int* in_sizes, int n_in,
                              void* d_out, int out_size) {
    const float* x    = (const float*)d_in[0];
    const float* sty  = (const float*)d_in[1];
    const float* affw = (const float*)d_in[2];
    const float* affb = (const float*)d_in[3];
    const float* cw   = (const float*)d_in[4];
    float* out = (float*)d_out;

    wsq_zero_kernel<<<1024, 256>>>(cw, (float4*)out);
    affine_demod_kernel<<<B_, 512>>>(sty, affw, affb);
    {
        dim3 g(B_ * 8, 8);
        build_x2_kernel<<<g, 256>>>(x);
    }
    build_w2_kernel<<<288, 256>>>(cw);

    cudaFuncSetAttribute(conv_mma, cudaFuncAttributeMaxDynamicSharedMemorySize, SMEM_CONV);
    conv_mma<<<NCTA, 128, SMEM_CONV>>>(out);
}